// round 3
// baseline (speedup 1.0000x reference)
#include <cuda_runtime.h>
#include <cuda_bf16.h>
#include <cstdint>

// ---------------------------------------------------------------------------
// DMTet geometry, fully on-device. Outputs concatenated into d_out (float32):
//   [ verts (E*3) | faces (Fc*3) | verts_tetmesh (U*3) | tets_tetmesh (T*4) ]
// ---------------------------------------------------------------------------

#define MAXN 400000
#define MAXF 2000000
#define MAXS (6 * MAXF)            // max edge slots (6 per valid tet)
#define MAXTE (12 * MAXF)          // max all_tets entries
#define PRESCAP (MAXN + MAXS)      // presence domain [0, N+E)
#define NBLK_MAX ((PRESCAP + 2047) / 2048 + 2)
#define NWORDS ((MAXN + 31) / 32)
#define BCAP 96                    // local-memory bucket capacity

// classification bitmasks over tetindex (derived from NTRI/NTET tables)
#define M_NTRI1 0x6996             // ti with 1 triangle
#define M_NTRI2 0x1668             // ti with 2 triangles
#define M_NTET1 0x0116             // valid ti with 1 tet

__device__ const int c_BE[12] = {0,1,0,2,0,3,1,2,1,3,2,3};
__device__ const int c_TRI[16][6] = {
    {-1,-1,-1,-1,-1,-1},{1,0,2,-1,-1,-1},{4,0,3,-1,-1,-1},{1,4,2,1,3,4},
    {3,1,5,-1,-1,-1},{2,3,0,2,5,3},{1,4,0,1,5,4},{4,2,5,-1,-1,-1},
    {4,5,2,-1,-1,-1},{4,1,0,4,5,1},{3,2,0,3,5,2},{1,3,5,-1,-1,-1},
    {4,1,2,4,3,1},{3,0,4,-1,-1,-1},{2,0,1,-1,-1,-1},{-1,-1,-1,-1,-1,-1}};
__device__ const int c_TET[16][12] = {
    {-1,-1,-1,-1,-1,-1,-1,-1,-1,-1,-1,-1},{0,4,5,6,-1,-1,-1,-1,-1,-1,-1,-1},
    {1,4,8,7,-1,-1,-1,-1,-1,-1,-1,-1},{7,1,8,6,5,1,7,6,5,0,1,6},
    {2,5,7,9,-1,-1,-1,-1,-1,-1,-1,-1},{4,0,6,7,9,0,7,6,7,0,9,2},
    {4,1,9,8,5,1,9,4,5,1,2,9},{6,0,1,2,8,6,1,2,9,6,8,2},
    {3,6,9,8,-1,-1,-1,-1,-1,-1,-1,-1},{5,0,4,8,5,0,8,3,5,8,9,3},
    {1,4,7,3,4,7,6,3,9,6,7,3},{0,1,5,3,5,1,9,3,5,1,7,9},
    {5,2,3,7,3,6,5,8,3,5,7,8},{0,4,7,8,0,3,8,7,0,3,7,2},
    {4,1,2,3,4,3,2,5,4,3,5,6},{0,1,2,3,-1,-1,-1,-1,-1,-1,-1,-1}};

// ---- scratch (static device memory; no runtime allocation) ----
__device__ unsigned int g_occbits[NWORDS];
__device__ unsigned char g_ti[MAXF];
__device__ int4 g_cls[MAXF];               // exclusive prefixes: nt1, nt2, ntt1, inner
__device__ int g_bcnt[MAXN];
__device__ int g_bstart[MAXN];             // after scatter: bucket END
__device__ unsigned long long g_bdata[MAXS];
__device__ int g_idxmap[MAXS];
__device__ int g_crossCnt[MAXN];
__device__ int g_crossX[MAXN];
__device__ unsigned long long g_epair[MAXS];
__device__ int g_allTets[MAXTE];
__device__ unsigned char g_present[PRESCAP];
__device__ int g_presX[PRESCAP];
__device__ int g_bsums[NBLK_MAX];
__device__ int4 g_bsums4[(MAXF + 2047) / 2048 + 2];
// meta: 0 NT1  1 NT2  2 NTT1  3 INNER  4 E  5 U
//       6 facesOff(3E)  7 trows  8 vtOff  9 tetsOff  10 scratch
__device__ int g_meta[16];

__device__ __forceinline__ int occ_of(int v) {
    return (g_occbits[v >> 5] >> (v & 31)) & 1;
}

// ---------------------------------------------------------------------------
// scans
// ---------------------------------------------------------------------------
__global__ void k_scan_partial_int(const int* in, int n, int* bsums) {
    __shared__ int sh[256];
    int b = blockIdx.x, tid = threadIdx.x;
    int base = b * 2048 + tid * 8;
    int s = 0;
#pragma unroll
    for (int j = 0; j < 8; j++) { int i = base + j; if (i < n) s += in[i]; }
    sh[tid] = s; __syncthreads();
    for (int o = 128; o > 0; o >>= 1) { if (tid < o) sh[tid] += sh[tid + o]; __syncthreads(); }
    if (tid == 0) bsums[b] = sh[0];
}

__global__ void k_scan_partial_u8(const unsigned char* in, int n, int* bsums) {
    __shared__ int sh[256];
    int b = blockIdx.x, tid = threadIdx.x;
    int base = b * 2048 + tid * 8;
    int s = 0;
#pragma unroll
    for (int j = 0; j < 8; j++) { int i = base + j; if (i < n) s += in[i]; }
    sh[tid] = s; __syncthreads();
    for (int o = 128; o > 0; o >>= 1) { if (tid < o) sh[tid] += sh[tid + o]; __syncthreads(); }
    if (tid == 0) bsums[b] = sh[0];
}

__global__ void k_scan_single(int* bsums, int nb, int* totalOut) {
    __shared__ int sh[1024];
    int tid = threadIdx.x;
    int carry = 0;
    for (int base = 0; base < nb; base += 1024) {
        int i = base + tid;
        int v = (i < nb) ? bsums[i] : 0;
        sh[tid] = v; __syncthreads();
        for (int o = 1; o < 1024; o <<= 1) {
            int t = (tid >= o) ? sh[tid - o] : 0;
            __syncthreads(); sh[tid] += t; __syncthreads();
        }
        if (i < nb) bsums[i] = carry + sh[tid] - v;
        int tot = sh[1023]; __syncthreads();
        carry += tot;
    }
    if (tid == 0 && totalOut) *totalOut = carry;
}

__global__ void k_scan_final_int(const int* in, int n, const int* bsums, int* outp) {
    __shared__ int sh[256];
    int b = blockIdx.x, tid = threadIdx.x;
    int base = b * 2048 + tid * 8;
    int v[8]; int s = 0;
#pragma unroll
    for (int j = 0; j < 8; j++) { int i = base + j; v[j] = (i < n) ? in[i] : 0; s += v[j]; }
    sh[tid] = s; __syncthreads();
    for (int o = 1; o < 256; o <<= 1) {
        int t = (tid >= o) ? sh[tid - o] : 0;
        __syncthreads(); sh[tid] += t; __syncthreads();
    }
    int run = bsums[b] + sh[tid] - s;
#pragma unroll
    for (int j = 0; j < 8; j++) { int i = base + j; if (i < n) outp[i] = run; run += v[j]; }
}

__global__ void k_scan_final_u8(const unsigned char* in, int n, const int* bsums, int* outp) {
    __shared__ int sh[256];
    int b = blockIdx.x, tid = threadIdx.x;
    int base = b * 2048 + tid * 8;
    int v[8]; int s = 0;
#pragma unroll
    for (int j = 0; j < 8; j++) { int i = base + j; v[j] = (i < n) ? (int)in[i] : 0; s += v[j]; }
    sh[tid] = s; __syncthreads();
    for (int o = 1; o < 256; o <<= 1) {
        int t = (tid >= o) ? sh[tid - o] : 0;
        __syncthreads(); sh[tid] += t; __syncthreads();
    }
    int run = bsums[b] + sh[tid] - s;
#pragma unroll
    for (int j = 0; j < 8; j++) { int i = base + j; if (i < n) outp[i] = run; run += v[j]; }
}

// ---- 4-component classification scan over g_ti ----
__device__ __forceinline__ int4 cls_val(int t) {
    int4 v;
    v.x = (M_NTRI1 >> t) & 1;
    v.y = (M_NTRI2 >> t) & 1;
    v.z = (M_NTET1 >> t) & 1;
    v.w = (t == 15) ? 1 : 0;
    return v;
}

__global__ void k_cls_partial(int F) {
    __shared__ int sx[256], sy[256], sz[256], sw[256];
    int b = blockIdx.x, tid = threadIdx.x;
    int base = b * 2048 + tid * 8;
    int4 s = {0, 0, 0, 0};
#pragma unroll
    for (int j = 0; j < 8; j++) {
        int i = base + j;
        if (i < F) {
            int4 v = cls_val(g_ti[i]);
            s.x += v.x; s.y += v.y; s.z += v.z; s.w += v.w;
        }
    }
    sx[tid] = s.x; sy[tid] = s.y; sz[tid] = s.z; sw[tid] = s.w;
    __syncthreads();
    for (int o = 128; o > 0; o >>= 1) {
        if (tid < o) { sx[tid] += sx[tid+o]; sy[tid] += sy[tid+o]; sz[tid] += sz[tid+o]; sw[tid] += sw[tid+o]; }
        __syncthreads();
    }
    if (tid == 0) { int4 r = {sx[0], sy[0], sz[0], sw[0]}; g_bsums4[b] = r; }
}

__global__ void k_scan_single4(int nb) {
    __shared__ int sh[1024];
    int* bs = (int*)g_bsums4;
    int tid = threadIdx.x;
    for (int c = 0; c < 4; c++) {
        int carry = 0;
        for (int base = 0; base < nb; base += 1024) {
            int i = base + tid;
            int v = (i < nb) ? bs[i * 4 + c] : 0;
            sh[tid] = v; __syncthreads();
            for (int o = 1; o < 1024; o <<= 1) {
                int t = (tid >= o) ? sh[tid - o] : 0;
                __syncthreads(); sh[tid] += t; __syncthreads();
            }
            if (i < nb) bs[i * 4 + c] = carry + sh[tid] - v;
            int tot = sh[1023]; __syncthreads();
            carry += tot;
        }
        if (tid == 0) g_meta[c] = carry;
        __syncthreads();
    }
}

__global__ void k_cls_final(int F) {
    __shared__ int sx[256], sy[256], sz[256], sw[256];
    int b = blockIdx.x, tid = threadIdx.x;
    int base = b * 2048 + tid * 8;
    int4 v[8]; int4 s = {0, 0, 0, 0};
#pragma unroll
    for (int j = 0; j < 8; j++) {
        int i = base + j;
        v[j] = (i < F) ? cls_val(g_ti[i]) : make_int4(0, 0, 0, 0);
        s.x += v[j].x; s.y += v[j].y; s.z += v[j].z; s.w += v[j].w;
    }
    sx[tid] = s.x; sy[tid] = s.y; sz[tid] = s.z; sw[tid] = s.w;
    __syncthreads();
    for (int o = 1; o < 256; o <<= 1) {
        int tx = (tid >= o) ? sx[tid-o] : 0; int ty = (tid >= o) ? sy[tid-o] : 0;
        int tz = (tid >= o) ? sz[tid-o] : 0; int tw = (tid >= o) ? sw[tid-o] : 0;
        __syncthreads();
        sx[tid] += tx; sy[tid] += ty; sz[tid] += tz; sw[tid] += tw;
        __syncthreads();
    }
    int4 bb = g_bsums4[b];
    int4 run = {bb.x + sx[tid] - s.x, bb.y + sy[tid] - s.y, bb.z + sz[tid] - s.z, bb.w + sw[tid] - s.w};
#pragma unroll
    for (int j = 0; j < 8; j++) {
        int i = base + j;
        if (i < F) g_cls[i] = run;
        run.x += v[j].x; run.y += v[j].y; run.z += v[j].z; run.w += v[j].w;
    }
}

// ---------------------------------------------------------------------------
// pipeline kernels
// ---------------------------------------------------------------------------
__global__ void k_fill_int(int* p, int v, int n) {
    int i = blockIdx.x * blockDim.x + threadIdx.x;
    if (i < n) p[i] = v;
}

__global__ void k_occbits(const float* sdf, const float* th, int N, int NW) {
    int i = blockIdx.x * blockDim.x + threadIdx.x;
    float t = th[0];
    bool p = false;
    if (i < N) { float s = sdf[i]; p = (s > 0.f && s <= t); }
    unsigned m = __ballot_sync(0xffffffffu, p);
    if ((threadIdx.x & 31) == 0 && (i >> 5) < NW) g_occbits[i >> 5] = m;
}

// compute tetindex + per-bucket edge counts in one pass over tet
__global__ void k_ti_count(const int4* tet, int F) {
    int f = blockIdx.x * blockDim.x + threadIdx.x;
    if (f >= F) return;
    int4 q = tet[f];
    int t = occ_of(q.x) | (occ_of(q.y) << 1) | (occ_of(q.z) << 2) | (occ_of(q.w) << 3);
    g_ti[f] = (unsigned char)t;
    if (t == 0 || t == 15) return;
    int qq[4] = {q.x, q.y, q.z, q.w};
#pragma unroll
    for (int k = 0; k < 6; k++) {
        int a = qq[c_BE[2 * k]], b = qq[c_BE[2 * k + 1]];
        atomicAdd(&g_bcnt[a < b ? a : b], 1);
    }
}

__global__ void k_scatter(const int4* tet, int F) {
    int f = blockIdx.x * blockDim.x + threadIdx.x;
    if (f >= F) return;
    int t = g_ti[f];
    if (t == 0 || t == 15) return;
    int4 cls = g_cls[f];
    int r = cls.x + cls.y;   // validX
    int4 q = tet[f];
    int qq[4] = {q.x, q.y, q.z, q.w};
#pragma unroll
    for (int k = 0; k < 6; k++) {
        int a = qq[c_BE[2 * k]], b = qq[c_BE[2 * k + 1]];
        int lo = a < b ? a : b, hi = a < b ? b : a;
        int pos = atomicAdd(&g_bstart[lo], 1);
        g_bdata[pos] = ((unsigned long long)(unsigned)hi << 32) | (unsigned)(r * 6 + k);
    }
}

__global__ void k_bsort(int N) {
    int a = blockIdx.x * blockDim.x + threadIdx.x;
    if (a >= N) return;
    int n = g_bcnt[a];
    long long s = (long long)g_bstart[a] - n;   // bstart is now bucket END
    int occa = occ_of(a);
    int c = 0;
    if (n <= BCAP) {
        unsigned long long loc[BCAP];
        for (int i = 0; i < n; i++) loc[i] = g_bdata[s + i];
        for (int i = 1; i < n; i++) {
            unsigned long long key = loc[i];
            int j = i - 1;
            while (j >= 0 && loc[j] > key) { loc[j + 1] = loc[j]; j--; }
            loc[j + 1] = key;
        }
        long long prev = -1;
        for (int i = 0; i < n; i++) {
            int b = (int)(loc[i] >> 32);
            if (b != prev) { c += occa ^ occ_of(b); prev = b; }
        }
    } else {
        // rare fallback: sort in-place in global, leaving it sorted for k_bassign
        for (int i = 1; i < n; i++) {
            unsigned long long key = g_bdata[s + i];
            int j = i - 1;
            while (j >= 0 && g_bdata[s + j] > key) { g_bdata[s + j + 1] = g_bdata[s + j]; j--; }
            g_bdata[s + j + 1] = key;
        }
        long long prev = -1;
        for (int i = 0; i < n; i++) {
            int b = (int)(g_bdata[s + i] >> 32);
            if (b != prev) { c += occa ^ occ_of(b); prev = b; }
        }
    }
    g_crossCnt[a] = c;
}

__global__ void k_bassign(int N) {
    int a = blockIdx.x * blockDim.x + threadIdx.x;
    if (a >= N) return;
    int n = g_bcnt[a];
    long long s = (long long)g_bstart[a] - n;
    int base = g_crossX[a];
    int occa = occ_of(a);
    long long prev = -1;
    int c = 0, mv = -1;
    if (n <= BCAP) {
        unsigned long long loc[BCAP];
        for (int i = 0; i < n; i++) loc[i] = g_bdata[s + i];
        for (int i = 1; i < n; i++) {
            unsigned long long key = loc[i];
            int j = i - 1;
            while (j >= 0 && loc[j] > key) { loc[j + 1] = loc[j]; j--; }
            loc[j + 1] = key;
        }
        for (int i = 0; i < n; i++) {
            unsigned long long d = loc[i];
            int b = (int)(d >> 32);
            int slot = (int)(d & 0xffffffffu);
            if (b != prev) {
                if (occa ^ occ_of(b)) {
                    int eid = base + c;
                    g_epair[eid] = ((unsigned long long)(unsigned)a << 32) | (unsigned)b;
                    mv = eid; c++;
                } else mv = -1;
                prev = b;
            }
            g_idxmap[slot] = mv;
        }
    } else {
        // fallback: g_bdata already sorted by k_bsort
        for (int i = 0; i < n; i++) {
            unsigned long long d = g_bdata[s + i];
            int b = (int)(d >> 32);
            int slot = (int)(d & 0xffffffffu);
            if (b != prev) {
                if (occa ^ occ_of(b)) {
                    int eid = base + c;
                    g_epair[eid] = ((unsigned long long)(unsigned)a << 32) | (unsigned)b;
                    mv = eid; c++;
                } else mv = -1;
                prev = b;
            }
            g_idxmap[slot] = mv;
        }
    }
}

__global__ void k_meta1() {
    int NT1 = g_meta[0], NT2 = g_meta[1], NTT1 = g_meta[2], INNER = g_meta[3];
    int E = g_meta[4];
    int NTT3 = NT1 + NT2 - NTT1;
    g_meta[6] = 3 * E;
    g_meta[7] = NTT1 + 3 * NTT3 + INNER;
    g_meta[8] = 3 * E + 3 * (NT1 + 2 * NT2);
}

__global__ void k_meta2() {
    g_meta[9] = g_meta[8] + 3 * g_meta[5];
}

__global__ void k_verts(const float* pos, const float* sdf, const float* th, float* out) {
    int e = blockIdx.x * blockDim.x + threadIdx.x;
    if (e >= g_meta[4]) return;
    unsigned long long p = g_epair[e];
    int a = (int)(p >> 32), b = (int)(p & 0xffffffffu);
    float t = th[0];
    float s0 = sdf[a], s1 = sdf[b];
    if (s0 > 0.f && s1 > 0.f) { s0 -= t; s1 -= t; }
    float inv = 1.f / (s0 - s1);
    float w0 = -s1 * inv, w1 = s0 * inv;
#pragma unroll
    for (int c = 0; c < 3; c++)
        out[e * 3 + c] = pos[a * 3 + c] * w0 + pos[b * 3 + c] * w1;
}

// fused: faces emission + tetmesh connectivity build + presence marking
__global__ void k_emit(const int4* tet, float* out, int F, int N) {
    int f = blockIdx.x * blockDim.x + threadIdx.x;
    if (f >= F) return;
    int t = g_ti[f];
    if (t == 0) return;
    int4 cls = g_cls[f];
    int4 q = tet[f];
    int qq[4] = {q.x, q.y, q.z, q.w};
    if (t == 15) {
        int NTT3 = g_meta[0] + g_meta[1] - g_meta[2];
        int row = g_meta[2] + 3 * NTT3 + cls.w;
#pragma unroll
        for (int j = 0; j < 4; j++) {
            g_allTets[row * 4 + j] = qq[j];
            g_present[qq[j]] = 1;
        }
        return;
    }
    int r = cls.x + cls.y;          // validX
    int foff = g_meta[6];
    // faces
    if ((M_NTRI1 >> t) & 1) {
        int row = cls.x;
#pragma unroll
        for (int j = 0; j < 3; j++)
            out[foff + row * 3 + j] = (float)g_idxmap[r * 6 + c_TRI[t][j]];
    } else {
        int row = g_meta[0] + 2 * cls.y;
#pragma unroll
        for (int j = 0; j < 6; j++)
            out[foff + row * 3 + j] = (float)g_idxmap[r * 6 + c_TRI[t][j]];
    }
    // tets
    if ((M_NTET1 >> t) & 1) {
        int row = cls.z;
#pragma unroll
        for (int j = 0; j < 4; j++) {
            int e = c_TET[t][j];
            int val = (e < 4) ? qq[e] : (g_idxmap[r * 6 + e - 4] + N);
            g_allTets[row * 4 + j] = val;
            g_present[val] = 1;
        }
    } else {
        int row = g_meta[2] + 3 * (r - cls.z);
#pragma unroll
        for (int m = 0; m < 12; m++) {
            int e = c_TET[t][m];
            int val = (e < 4) ? qq[e] : (g_idxmap[r * 6 + e - 4] + N);
            g_allTets[row * 4 + m] = val;
            g_present[val] = 1;
        }
    }
}

__global__ void k_vt(const float* pos, float* out, int N, int PL) {
    int idx = blockIdx.x * blockDim.x + threadIdx.x;
    if (idx >= PL) return;
    if (!g_present[idx]) return;
    int uid = g_presX[idx];
    float x, y, z;
    if (idx < N) {
        x = pos[idx * 3 + 0]; y = pos[idx * 3 + 1]; z = pos[idx * 3 + 2];
    } else {
        int e = idx - N;
        x = out[e * 3 + 0]; y = out[e * 3 + 1]; z = out[e * 3 + 2];
    }
    int o = g_meta[8];
    out[o + uid * 3 + 0] = x;
    out[o + uid * 3 + 1] = y;
    out[o + uid * 3 + 2] = z;
}

__global__ void k_tout(float* out) {
    int i = blockIdx.x * blockDim.x + threadIdx.x;
    if (i >= 4 * g_meta[7]) return;
    out[g_meta[9] + i] = (float)g_presX[g_allTets[i]];
}

// ---------------------------------------------------------------------------
// host launcher
// ---------------------------------------------------------------------------
static inline int gb(long long n) { return (int)((n + 255) / 256); }

static void run_scan_int(const int* in, int n, int* outPrefix, int* totalOut, int* bsums) {
    int nb = (n + 2047) / 2048;
    k_scan_partial_int<<<nb, 256>>>(in, n, bsums);
    k_scan_single<<<1, 1024>>>(bsums, nb, totalOut);
    k_scan_final_int<<<nb, 256>>>(in, n, bsums, outPrefix);
}

static void run_scan_u8(const unsigned char* in, int n, int* outPrefix, int* totalOut, int* bsums) {
    int nb = (n + 2047) / 2048;
    k_scan_partial_u8<<<nb, 256>>>(in, n, bsums);
    k_scan_single<<<1, 1024>>>(bsums, nb, totalOut);
    k_scan_final_u8<<<nb, 256>>>(in, n, bsums, outPrefix);
}

extern "C" void kernel_launch(void* const* d_in, const int* in_sizes, int n_in,
                              void* d_out, int out_size) {
    const float* pos = (const float*)d_in[0];
    const float* sdf = (const float*)d_in[1];
    const int4* tet = (const int4*)d_in[2];
    const float* thick = (const float*)d_in[3];
    float* out = (float*)d_out;

    int N = in_sizes[1];
    int F = in_sizes[2] / 4;
    if (N > MAXN) N = MAXN;
    if (F > MAXF) F = MAXF;
    int NW = (N + 31) / 32;
    int PL = N + MAXS;

    int *p_bcnt, *p_bstart, *p_crossCnt, *p_crossX, *p_presX, *p_bsums, *p_meta;
    unsigned char* p_present;
    cudaGetSymbolAddress((void**)&p_bcnt, g_bcnt);
    cudaGetSymbolAddress((void**)&p_bstart, g_bstart);
    cudaGetSymbolAddress((void**)&p_crossCnt, g_crossCnt);
    cudaGetSymbolAddress((void**)&p_crossX, g_crossX);
    cudaGetSymbolAddress((void**)&p_present, g_present);
    cudaGetSymbolAddress((void**)&p_presX, g_presX);
    cudaGetSymbolAddress((void**)&p_bsums, g_bsums);
    cudaGetSymbolAddress((void**)&p_meta, g_meta);

    // 0. zero bucket counts + presence (graph replays must reset state)
    k_fill_int<<<gb(N), 256>>>(p_bcnt, 0, N);
    k_fill_int<<<gb(PL / 4), 256>>>((int*)p_present, 0, PL / 4);

    // 1. occupancy bitmask + tetindex + per-bucket edge counts (one tet pass)
    k_occbits<<<gb((long long)NW * 32), 256>>>(sdf, thick, N, NW);
    k_ti_count<<<gb(F), 256>>>(tet, F);

    // 2. fused 4-component classification scan (nt1, nt2, ntt1, inner)
    {
        int nb = (F + 2047) / 2048;
        k_cls_partial<<<nb, 256>>>(F);
        k_scan_single4<<<1, 1024>>>(nb);
        k_cls_final<<<nb, 256>>>(F);
    }

    // 3. bucket offsets + edge scatter (bstart becomes bucket end)
    run_scan_int(p_bcnt, N, p_bstart, p_meta + 10, p_bsums);
    k_scatter<<<gb(F), 256>>>(tet, F);

    // 4. per-bucket local sort: crossing counts, then edge id assignment
    k_bsort<<<gb(N), 256>>>(N);
    run_scan_int(p_crossCnt, N, p_crossX, p_meta + 4, p_bsums);
    k_bassign<<<gb(N), 256>>>(N);
    k_meta1<<<1, 1>>>();

    // 5. interpolated vertices (region 0)
    k_verts<<<gb(MAXS), 256>>>(pos, sdf, thick, out);

    // 6. faces (region 1) + tetmesh connectivity + presence marks (fused)
    k_emit<<<gb(F), 256>>>(tet, out, F, N);

    // 7. presence scan -> sorted-unique ids
    run_scan_u8(p_present, PL, p_presX, p_meta + 5, p_bsums);
    k_meta2<<<1, 1>>>();

    // 8. verts_tetmesh (region 2) + tets_tetmesh (region 3)
    k_vt<<<gb(PL), 256>>>(pos, out, N, PL);
    k_tout<<<gb(MAXTE), 256>>>(out);
}

// round 5
// speedup vs baseline: 1.5754x; 1.5754x over previous
#include <cuda_runtime.h>
#include <cuda_bf16.h>
#include <cstdint>

// ---------------------------------------------------------------------------
// DMTet geometry, fully on-device. Outputs concatenated into d_out (float32):
//   [ verts (E*3) | faces (Fc*3) | verts_tetmesh (U*3) | tets_tetmesh (T*4) ]
// ---------------------------------------------------------------------------

#define MAXN 400000
#define MAXF 2000000
#define MAXS (6 * MAXF)            // max edge slots (6 per valid tet)
#define MAXTE (12 * MAXF)          // max all_tets entries
#define PRESCAP (MAXN + MAXS)      // presence domain [0, N+E)
#define NBLK_MAX ((PRESCAP + 2047) / 2048 + 2)
#define NWORDS ((MAXN + 31) / 32)

// classification bitmasks over tetindex (derived from NTRI/NTET tables)
#define M_NTRI1 0x6996             // ti with 1 triangle
#define M_NTRI2 0x1668             // ti with 2 triangles
#define M_NTET1 0x0116             // valid ti with 1 tet

__device__ const int c_BE[12] = {0,1,0,2,0,3,1,2,1,3,2,3};
__device__ const int c_TRI[16][6] = {
    {-1,-1,-1,-1,-1,-1},{1,0,2,-1,-1,-1},{4,0,3,-1,-1,-1},{1,4,2,1,3,4},
    {3,1,5,-1,-1,-1},{2,3,0,2,5,3},{1,4,0,1,5,4},{4,2,5,-1,-1,-1},
    {4,5,2,-1,-1,-1},{4,1,0,4,5,1},{3,2,0,3,5,2},{1,3,5,-1,-1,-1},
    {4,1,2,4,3,1},{3,0,4,-1,-1,-1},{2,0,1,-1,-1,-1},{-1,-1,-1,-1,-1,-1}};
__device__ const int c_TET[16][12] = {
    {-1,-1,-1,-1,-1,-1,-1,-1,-1,-1,-1,-1},{0,4,5,6,-1,-1,-1,-1,-1,-1,-1,-1},
    {1,4,8,7,-1,-1,-1,-1,-1,-1,-1,-1},{7,1,8,6,5,1,7,6,5,0,1,6},
    {2,5,7,9,-1,-1,-1,-1,-1,-1,-1,-1},{4,0,6,7,9,0,7,6,7,0,9,2},
    {4,1,9,8,5,1,9,4,5,1,2,9},{6,0,1,2,8,6,1,2,9,6,8,2},
    {3,6,9,8,-1,-1,-1,-1,-1,-1,-1,-1},{5,0,4,8,5,0,8,3,5,8,9,3},
    {1,4,7,3,4,7,6,3,9,6,7,3},{0,1,5,3,5,1,9,3,5,1,7,9},
    {5,2,3,7,3,6,5,8,3,5,7,8},{0,4,7,8,0,3,8,7,0,3,7,2},
    {4,1,2,3,4,3,2,5,4,3,5,6},{0,1,2,3,-1,-1,-1,-1,-1,-1,-1,-1}};

// ---- scratch (static device memory; no runtime allocation) ----
__device__ unsigned int g_occbits[NWORDS];
__device__ unsigned char g_ti[MAXF];
__device__ int4 g_cls[MAXF];               // exclusive prefixes: nt1, nt2, ntt1, inner
__device__ int g_bcnt[MAXN];
__device__ int g_bstart[MAXN];             // after scatter: bucket END
__device__ unsigned long long g_bdata[MAXS];
__device__ int g_idxmap[MAXS];
__device__ int g_crossCnt[MAXN];
__device__ int g_crossX[MAXN];
__device__ int g_allTets[MAXTE];
__device__ unsigned char g_present[PRESCAP];
__device__ int g_presX[PRESCAP];
__device__ int g_bsums[NBLK_MAX];
__device__ int4 g_bsums4[(MAXF + 2047) / 2048 + 2];
// meta: 0 NT1  1 NT2  2 NTT1  3 INNER  4 E  5 U
//       6 facesOff(3E)  7 trows  8 vtOff  9 tetsOff  10 scratch
__device__ int g_meta[16];

__device__ __forceinline__ int occ_of(int v) {
    return (g_occbits[v >> 5] >> (v & 31)) & 1;
}

// 32-lane bitonic sort over u64 keys, all in registers via shfl_xor.
__device__ __forceinline__ unsigned long long warp_bitonic32(unsigned long long key, int lane) {
#pragma unroll
    for (int k = 2; k <= 32; k <<= 1) {
#pragma unroll
        for (int j = k >> 1; j > 0; j >>= 1) {
            unsigned long long other = __shfl_xor_sync(0xffffffffu, key, j);
            bool up = ((lane & k) == 0);
            bool lower = ((lane & j) == 0);
            bool keepMin = (up == lower);
            unsigned long long mn = key < other ? key : other;
            unsigned long long mx = key < other ? other : key;
            key = keepMin ? mn : mx;
        }
    }
    return key;
}

// ---------------------------------------------------------------------------
// scans
// ---------------------------------------------------------------------------
__global__ void k_scan_partial_int(const int* in, int n, int* bsums) {
    __shared__ int sh[256];
    int b = blockIdx.x, tid = threadIdx.x;
    int base = b * 2048 + tid * 8;
    int s = 0;
#pragma unroll
    for (int j = 0; j < 8; j++) { int i = base + j; if (i < n) s += in[i]; }
    sh[tid] = s; __syncthreads();
    for (int o = 128; o > 0; o >>= 1) { if (tid < o) sh[tid] += sh[tid + o]; __syncthreads(); }
    if (tid == 0) bsums[b] = sh[0];
}

__global__ void k_scan_partial_u8(const unsigned char* in, int n, int* bsums) {
    __shared__ int sh[256];
    int b = blockIdx.x, tid = threadIdx.x;
    int base = b * 2048 + tid * 8;
    int s = 0;
#pragma unroll
    for (int j = 0; j < 8; j++) { int i = base + j; if (i < n) s += in[i]; }
    sh[tid] = s; __syncthreads();
    for (int o = 128; o > 0; o >>= 1) { if (tid < o) sh[tid] += sh[tid + o]; __syncthreads(); }
    if (tid == 0) bsums[b] = sh[0];
}

__global__ void k_scan_single(int* bsums, int nb, int* totalOut) {
    __shared__ int sh[1024];
    int tid = threadIdx.x;
    int carry = 0;
    for (int base = 0; base < nb; base += 1024) {
        int i = base + tid;
        int v = (i < nb) ? bsums[i] : 0;
        sh[tid] = v; __syncthreads();
        for (int o = 1; o < 1024; o <<= 1) {
            int t = (tid >= o) ? sh[tid - o] : 0;
            __syncthreads(); sh[tid] += t; __syncthreads();
        }
        if (i < nb) bsums[i] = carry + sh[tid] - v;
        int tot = sh[1023]; __syncthreads();
        carry += tot;
    }
    if (tid == 0 && totalOut) *totalOut = carry;
}

__global__ void k_scan_final_int(const int* in, int n, const int* bsums, int* outp) {
    __shared__ int sh[256];
    int b = blockIdx.x, tid = threadIdx.x;
    int base = b * 2048 + tid * 8;
    int v[8]; int s = 0;
#pragma unroll
    for (int j = 0; j < 8; j++) { int i = base + j; v[j] = (i < n) ? in[i] : 0; s += v[j]; }
    sh[tid] = s; __syncthreads();
    for (int o = 1; o < 256; o <<= 1) {
        int t = (tid >= o) ? sh[tid - o] : 0;
        __syncthreads(); sh[tid] += t; __syncthreads();
    }
    int run = bsums[b] + sh[tid] - s;
#pragma unroll
    for (int j = 0; j < 8; j++) { int i = base + j; if (i < n) outp[i] = run; run += v[j]; }
}

__global__ void k_scan_final_u8(const unsigned char* in, int n, const int* bsums, int* outp) {
    __shared__ int sh[256];
    int b = blockIdx.x, tid = threadIdx.x;
    int base = b * 2048 + tid * 8;
    int v[8]; int s = 0;
#pragma unroll
    for (int j = 0; j < 8; j++) { int i = base + j; v[j] = (i < n) ? (int)in[i] : 0; s += v[j]; }
    sh[tid] = s; __syncthreads();
    for (int o = 1; o < 256; o <<= 1) {
        int t = (tid >= o) ? sh[tid - o] : 0;
        __syncthreads(); sh[tid] += t; __syncthreads();
    }
    int run = bsums[b] + sh[tid] - s;
#pragma unroll
    for (int j = 0; j < 8; j++) { int i = base + j; if (i < n) outp[i] = run; run += v[j]; }
}

// ---- 4-component classification scan over g_ti ----
__device__ __forceinline__ int4 cls_val(int t) {
    int4 v;
    v.x = (M_NTRI1 >> t) & 1;
    v.y = (M_NTRI2 >> t) & 1;
    v.z = (M_NTET1 >> t) & 1;
    v.w = (t == 15) ? 1 : 0;
    return v;
}

__global__ void k_cls_partial(int F) {
    __shared__ int sx[256], sy[256], sz[256], sw[256];
    int b = blockIdx.x, tid = threadIdx.x;
    int base = b * 2048 + tid * 8;
    int4 s = {0, 0, 0, 0};
#pragma unroll
    for (int j = 0; j < 8; j++) {
        int i = base + j;
        if (i < F) {
            int4 v = cls_val(g_ti[i]);
            s.x += v.x; s.y += v.y; s.z += v.z; s.w += v.w;
        }
    }
    sx[tid] = s.x; sy[tid] = s.y; sz[tid] = s.z; sw[tid] = s.w;
    __syncthreads();
    for (int o = 128; o > 0; o >>= 1) {
        if (tid < o) { sx[tid] += sx[tid+o]; sy[tid] += sy[tid+o]; sz[tid] += sz[tid+o]; sw[tid] += sw[tid+o]; }
        __syncthreads();
    }
    if (tid == 0) { int4 r = {sx[0], sy[0], sz[0], sw[0]}; g_bsums4[b] = r; }
}

__global__ void k_scan_single4(int nb) {
    __shared__ int sh[1024];
    int* bs = (int*)g_bsums4;
    int tid = threadIdx.x;
    for (int c = 0; c < 4; c++) {
        int carry = 0;
        for (int base = 0; base < nb; base += 1024) {
            int i = base + tid;
            int v = (i < nb) ? bs[i * 4 + c] : 0;
            sh[tid] = v; __syncthreads();
            for (int o = 1; o < 1024; o <<= 1) {
                int t = (tid >= o) ? sh[tid - o] : 0;
                __syncthreads(); sh[tid] += t; __syncthreads();
            }
            if (i < nb) bs[i * 4 + c] = carry + sh[tid] - v;
            int tot = sh[1023]; __syncthreads();
            carry += tot;
        }
        if (tid == 0) g_meta[c] = carry;
        __syncthreads();
    }
}

__global__ void k_cls_final(int F) {
    __shared__ int sx[256], sy[256], sz[256], sw[256];
    int b = blockIdx.x, tid = threadIdx.x;
    int base = b * 2048 + tid * 8;
    int4 v[8]; int4 s = {0, 0, 0, 0};
#pragma unroll
    for (int j = 0; j < 8; j++) {
        int i = base + j;
        v[j] = (i < F) ? cls_val(g_ti[i]) : make_int4(0, 0, 0, 0);
        s.x += v[j].x; s.y += v[j].y; s.z += v[j].z; s.w += v[j].w;
    }
    sx[tid] = s.x; sy[tid] = s.y; sz[tid] = s.z; sw[tid] = s.w;
    __syncthreads();
    for (int o = 1; o < 256; o <<= 1) {
        int tx = (tid >= o) ? sx[tid-o] : 0; int ty = (tid >= o) ? sy[tid-o] : 0;
        int tz = (tid >= o) ? sz[tid-o] : 0; int tw = (tid >= o) ? sw[tid-o] : 0;
        __syncthreads();
        sx[tid] += tx; sy[tid] += ty; sz[tid] += tz; sw[tid] += tw;
        __syncthreads();
    }
    int4 bb = g_bsums4[b];
    int4 run = {bb.x + sx[tid] - s.x, bb.y + sy[tid] - s.y, bb.z + sz[tid] - s.z, bb.w + sw[tid] - s.w};
#pragma unroll
    for (int j = 0; j < 8; j++) {
        int i = base + j;
        if (i < F) g_cls[i] = run;
        run.x += v[j].x; run.y += v[j].y; run.z += v[j].z; run.w += v[j].w;
    }
}

// ---------------------------------------------------------------------------
// pipeline kernels
// ---------------------------------------------------------------------------
__global__ void k_fill_int(int* p, int v, int n) {
    int i = blockIdx.x * blockDim.x + threadIdx.x;
    if (i < n) p[i] = v;
}

__global__ void k_occbits(const float* sdf, const float* th, int N, int NW) {
    int i = blockIdx.x * blockDim.x + threadIdx.x;
    float t = th[0];
    bool p = false;
    if (i < N) { float s = sdf[i]; p = (s > 0.f && s <= t); }
    unsigned m = __ballot_sync(0xffffffffu, p);
    if ((threadIdx.x & 31) == 0 && (i >> 5) < NW) g_occbits[i >> 5] = m;
}

// compute tetindex + per-bucket edge counts in one pass over tet
__global__ void k_ti_count(const int4* tet, int F) {
    int f = blockIdx.x * blockDim.x + threadIdx.x;
    if (f >= F) return;
    int4 q = tet[f];
    int t = occ_of(q.x) | (occ_of(q.y) << 1) | (occ_of(q.z) << 2) | (occ_of(q.w) << 3);
    g_ti[f] = (unsigned char)t;
    if (t == 0 || t == 15) return;
    int qq[4] = {q.x, q.y, q.z, q.w};
#pragma unroll
    for (int k = 0; k < 6; k++) {
        int a = qq[c_BE[2 * k]], b = qq[c_BE[2 * k + 1]];
        atomicAdd(&g_bcnt[a < b ? a : b], 1);
    }
}

__global__ void k_scatter(const int4* tet, int F) {
    int f = blockIdx.x * blockDim.x + threadIdx.x;
    if (f >= F) return;
    int t = g_ti[f];
    if (t == 0 || t == 15) return;
    int4 cls = g_cls[f];
    int r = cls.x + cls.y;   // validX
    int4 q = tet[f];
    int qq[4] = {q.x, q.y, q.z, q.w};
#pragma unroll
    for (int k = 0; k < 6; k++) {
        int a = qq[c_BE[2 * k]], b = qq[c_BE[2 * k + 1]];
        int lo = a < b ? a : b, hi = a < b ? b : a;
        int pos = atomicAdd(&g_bstart[lo], 1);
        g_bdata[pos] = ((unsigned long long)(unsigned)hi << 32) | (unsigned)(r * 6 + k);
    }
}

// Phase 1: one warp per bucket. Register bitonic sort, ballot-based distinct
// crossing count. For rare n>32 buckets, lane 0 sorts in-place in global.
__global__ void k_bcount(int N) {
    int lane = threadIdx.x & 31;
    int b = (blockIdx.x * blockDim.x + threadIdx.x) >> 5;
    if (b >= N) return;
    int n = g_bcnt[b];
    if (n == 0) { if (lane == 0) g_crossCnt[b] = 0; return; }
    long long s = (long long)g_bstart[b] - n;   // bstart is bucket END
    int occa = occ_of(b);
    if (n <= 32) {
        unsigned long long key = (lane < n) ? g_bdata[s + lane] : ~0ull;
        key = warp_bitonic32(key, lane);
        int hi = (int)(key >> 32);
        unsigned long long prev = __shfl_up_sync(0xffffffffu, key, 1);
        bool isRep = (lane < n) && (lane == 0 || (int)(prev >> 32) != hi);
        bool cross = isRep && (occa ^ occ_of(hi));
        int c = __popc(__ballot_sync(0xffffffffu, cross));
        if (lane == 0) g_crossCnt[b] = c;
    } else {
        if (lane == 0) {
            for (int i = 1; i < n; i++) {
                unsigned long long key = g_bdata[s + i];
                int j = i - 1;
                while (j >= 0 && g_bdata[s + j] > key) { g_bdata[s + j + 1] = g_bdata[s + j]; j--; }
                g_bdata[s + j + 1] = key;
            }
            long long prev = -1; int c = 0;
            for (int i = 0; i < n; i++) {
                int hv = (int)(g_bdata[s + i] >> 32);
                if (hv != prev) { c += occa ^ occ_of(hv); prev = hv; }
            }
            g_crossCnt[b] = c;
        }
    }
}

// Phase 2: re-sort in registers, assign edge ids, write idxmap, and emit the
// interpolated vertex for each crossing rep lane (fused former k_verts).
__global__ void k_bemit(const float* pos, const float* sdf, const float* th,
                        float* out, int N) {
    int lane = threadIdx.x & 31;
    int b = (blockIdx.x * blockDim.x + threadIdx.x) >> 5;
    if (b >= N) return;
    int n = g_bcnt[b];
    if (n == 0) return;
    long long s = (long long)g_bstart[b] - n;
    int base = g_crossX[b];
    int occa = occ_of(b);
    if (n <= 32) {
        unsigned long long key = (lane < n) ? g_bdata[s + lane] : ~0ull;
        key = warp_bitonic32(key, lane);
        int hi = (int)(key >> 32);
        int slot = (int)(key & 0xffffffffu);
        unsigned long long prev = __shfl_up_sync(0xffffffffu, key, 1);
        bool isRep = (lane < n) && (lane == 0 || (int)(prev >> 32) != hi);
        bool cross = isRep && (occa ^ occ_of(hi));
        unsigned crossB = __ballot_sync(0xffffffffu, cross);
        unsigned repB = __ballot_sync(0xffffffffu, isRep);
        int rank = __popc(crossB & ((1u << lane) - 1));
        int eid = cross ? (base + rank) : -1;
        // propagate each lane's governing rep's eid (reps of non-crossing give -1)
        int repLane = 31 - __clz(repB & ((2u << lane) - 1) | 1u);
        int mv = __shfl_sync(0xffffffffu, eid, repLane);
        if (lane < n) g_idxmap[slot] = mv;
        if (cross) {
            float t = th[0];
            float s0 = sdf[b], s1 = sdf[hi];
            if (s0 > 0.f && s1 > 0.f) { s0 -= t; s1 -= t; }
            float inv = 1.f / (s0 - s1);
            float w0 = -s1 * inv, w1 = s0 * inv;
#pragma unroll
            for (int c = 0; c < 3; c++)
                out[eid * 3 + c] = pos[b * 3 + c] * w0 + pos[hi * 3 + c] * w1;
        }
    } else {
        if (lane == 0) {
            // g_bdata already sorted by k_bcount fallback
            long long prev = -1; int c = 0, mv = -1;
            for (int i = 0; i < n; i++) {
                unsigned long long d = g_bdata[s + i];
                int hv = (int)(d >> 32);
                int slot = (int)(d & 0xffffffffu);
                if (hv != prev) {
                    if (occa ^ occ_of(hv)) {
                        int eid = base + c;
                        float t = th[0];
                        float s0 = sdf[b], s1 = sdf[hv];
                        if (s0 > 0.f && s1 > 0.f) { s0 -= t; s1 -= t; }
                        float inv = 1.f / (s0 - s1);
                        float w0 = -s1 * inv, w1 = s0 * inv;
                        for (int cc = 0; cc < 3; cc++)
                            out[eid * 3 + cc] = pos[b * 3 + cc] * w0 + pos[hv * 3 + cc] * w1;
                        mv = eid; c++;
                    } else mv = -1;
                    prev = hv;
                }
                g_idxmap[slot] = mv;
            }
        }
    }
}

__global__ void k_meta1() {
    int NT1 = g_meta[0], NT2 = g_meta[1], NTT1 = g_meta[2], INNER = g_meta[3];
    int E = g_meta[4];
    int NTT3 = NT1 + NT2 - NTT1;
    g_meta[6] = 3 * E;
    g_meta[7] = NTT1 + 3 * NTT3 + INNER;
    g_meta[8] = 3 * E + 3 * (NT1 + 2 * NT2);
}

__global__ void k_meta2() {
    g_meta[9] = g_meta[8] + 3 * g_meta[5];
}

// fused: faces emission + tetmesh connectivity build + presence marking
__global__ void k_emit(const int4* tet, float* out, int F, int N) {
    int f = blockIdx.x * blockDim.x + threadIdx.x;
    if (f >= F) return;
    int t = g_ti[f];
    if (t == 0) return;
    int4 cls = g_cls[f];
    int4 q = tet[f];
    int qq[4] = {q.x, q.y, q.z, q.w};
    if (t == 15) {
        int NTT3 = g_meta[0] + g_meta[1] - g_meta[2];
        int row = g_meta[2] + 3 * NTT3 + cls.w;
#pragma unroll
        for (int j = 0; j < 4; j++) {
            g_allTets[row * 4 + j] = qq[j];
            g_present[qq[j]] = 1;
        }
        return;
    }
    int r = cls.x + cls.y;          // validX
    int foff = g_meta[6];
    // faces
    if ((M_NTRI1 >> t) & 1) {
        int row = cls.x;
#pragma unroll
        for (int j = 0; j < 3; j++)
            out[foff + row * 3 + j] = (float)g_idxmap[r * 6 + c_TRI[t][j]];
    } else {
        int row = g_meta[0] + 2 * cls.y;
#pragma unroll
        for (int j = 0; j < 6; j++)
            out[foff + row * 3 + j] = (float)g_idxmap[r * 6 + c_TRI[t][j]];
    }
    // tets
    if ((M_NTET1 >> t) & 1) {
        int row = cls.z;
#pragma unroll
        for (int j = 0; j < 4; j++) {
            int e = c_TET[t][j];
            int val = (e < 4) ? qq[e] : (g_idxmap[r * 6 + e - 4] + N);
            g_allTets[row * 4 + j] = val;
            g_present[val] = 1;
        }
    } else {
        int row = g_meta[2] + 3 * (r - cls.z);
#pragma unroll
        for (int m = 0; m < 12; m++) {
            int e = c_TET[t][m];
            int val = (e < 4) ? qq[e] : (g_idxmap[r * 6 + e - 4] + N);
            g_allTets[row * 4 + m] = val;
            g_present[val] = 1;
        }
    }
}

__global__ void k_vt(const float* pos, float* out, int N, int PL) {
    int idx = blockIdx.x * blockDim.x + threadIdx.x;
    if (idx >= PL) return;
    if (!g_present[idx]) return;
    int uid = g_presX[idx];
    float x, y, z;
    if (idx < N) {
        x = pos[idx * 3 + 0]; y = pos[idx * 3 + 1]; z = pos[idx * 3 + 2];
    } else {
        int e = idx - N;
        x = out[e * 3 + 0]; y = out[e * 3 + 1]; z = out[e * 3 + 2];
    }
    int o = g_meta[8];
    out[o + uid * 3 + 0] = x;
    out[o + uid * 3 + 1] = y;
    out[o + uid * 3 + 2] = z;
}

__global__ void k_tout(float* out) {
    int i = blockIdx.x * blockDim.x + threadIdx.x;
    if (i >= 4 * g_meta[7]) return;
    out[g_meta[9] + i] = (float)g_presX[g_allTets[i]];
}

// ---------------------------------------------------------------------------
// host launcher
// ---------------------------------------------------------------------------
static inline int gb(long long n) { return (int)((n + 255) / 256); }

static void run_scan_int(const int* in, int n, int* outPrefix, int* totalOut, int* bsums) {
    int nb = (n + 2047) / 2048;
    k_scan_partial_int<<<nb, 256>>>(in, n, bsums);
    k_scan_single<<<1, 1024>>>(bsums, nb, totalOut);
    k_scan_final_int<<<nb, 256>>>(in, n, bsums, outPrefix);
}

static void run_scan_u8(const unsigned char* in, int n, int* outPrefix, int* totalOut, int* bsums) {
    int nb = (n + 2047) / 2048;
    k_scan_partial_u8<<<nb, 256>>>(in, n, bsums);
    k_scan_single<<<1, 1024>>>(bsums, nb, totalOut);
    k_scan_final_u8<<<nb, 256>>>(in, n, bsums, outPrefix);
}

extern "C" void kernel_launch(void* const* d_in, const int* in_sizes, int n_in,
                              void* d_out, int out_size) {
    const float* pos = (const float*)d_in[0];
    const float* sdf = (const float*)d_in[1];
    const int4* tet = (const int4*)d_in[2];
    const float* thick = (const float*)d_in[3];
    float* out = (float*)d_out;

    int N = in_sizes[1];
    int F = in_sizes[2] / 4;
    if (N > MAXN) N = MAXN;
    if (F > MAXF) F = MAXF;
    int NW = (N + 31) / 32;
    int PL = N + MAXS;

    int *p_bcnt, *p_bstart, *p_crossCnt, *p_crossX, *p_presX, *p_bsums, *p_meta;
    unsigned char* p_present;
    cudaGetSymbolAddress((void**)&p_bcnt, g_bcnt);
    cudaGetSymbolAddress((void**)&p_bstart, g_bstart);
    cudaGetSymbolAddress((void**)&p_crossCnt, g_crossCnt);
    cudaGetSymbolAddress((void**)&p_crossX, g_crossX);
    cudaGetSymbolAddress((void**)&p_present, g_present);
    cudaGetSymbolAddress((void**)&p_presX, g_presX);
    cudaGetSymbolAddress((void**)&p_bsums, g_bsums);
    cudaGetSymbolAddress((void**)&p_meta, g_meta);

    // 0. zero bucket counts + presence (graph replays must reset state)
    k_fill_int<<<gb(N), 256>>>(p_bcnt, 0, N);
    k_fill_int<<<gb(PL / 4), 256>>>((int*)p_present, 0, PL / 4);

    // 1. occupancy bitmask + tetindex + per-bucket edge counts (one tet pass)
    k_occbits<<<gb((long long)NW * 32), 256>>>(sdf, thick, N, NW);
    k_ti_count<<<gb(F), 256>>>(tet, F);

    // 2. fused 4-component classification scan (nt1, nt2, ntt1, inner)
    {
        int nb = (F + 2047) / 2048;
        k_cls_partial<<<nb, 256>>>(F);
        k_scan_single4<<<1, 1024>>>(nb);
        k_cls_final<<<nb, 256>>>(F);
    }

    // 3. bucket offsets + edge scatter (bstart becomes bucket end)
    run_scan_int(p_bcnt, N, p_bstart, p_meta + 10, p_bsums);
    k_scatter<<<gb(F), 256>>>(tet, F);

    // 4. warp-per-bucket register sort: crossing counts -> prefix -> assignment
    //    (phase 2 also emits interpolated vertices, region 0)
    k_bcount<<<gb((long long)N * 32), 256>>>(N);
    run_scan_int(p_crossCnt, N, p_crossX, p_meta + 4, p_bsums);
    k_bemit<<<gb((long long)N * 32), 256>>>(pos, sdf, thick, out, N);
    k_meta1<<<1, 1>>>();

    // 5. faces (region 1) + tetmesh connectivity + presence marks (fused)
    k_emit<<<gb(F), 256>>>(tet, out, F, N);

    // 6. presence scan -> sorted-unique ids
    run_scan_u8(p_present, PL, p_presX, p_meta + 5, p_bsums);
    k_meta2<<<1, 1>>>();

    // 7. verts_tetmesh (region 2) + tets_tetmesh (region 3)
    k_vt<<<gb(PL), 256>>>(pos, out, N, PL);
    k_tout<<<gb(MAXTE), 256>>>(out);
}

// round 6
// speedup vs baseline: 1.7453x; 1.1078x over previous
#include <cuda_runtime.h>
#include <cuda_bf16.h>
#include <cstdint>

// ---------------------------------------------------------------------------
// DMTet geometry, fully on-device. Outputs concatenated into d_out (float32):
//   [ verts (E*3) | faces (Fc*3) | verts_tetmesh (U*3) | tets_tetmesh (T*4) ]
// ---------------------------------------------------------------------------

#define MAXN 400000
#define MAXF 2000000
#define MAXS (6 * MAXF)            // max edge slots (6 per valid tet)
#define MAXTE (12 * MAXF)          // max all_tets entries
#define PRESCAP (MAXN + MAXS)      // presence domain [0, N+E)
#define NBLK_MAX ((PRESCAP + 2047) / 2048 + 2)
#define NWORDS ((MAXN + 31) / 32)
#define NB256 ((MAXF + 255) / 256)

// classification bitmasks over tetindex
#define M_NTRI1 0x6996             // ti with 1 triangle
#define M_NTRI2 0x1668             // ti with 2 triangles
#define M_NTET1 0x0116             // valid ti with 1 tet

__device__ const int c_BE[12] = {0,1,0,2,0,3,1,2,1,3,2,3};
__device__ const int c_TRI[16][6] = {
    {-1,-1,-1,-1,-1,-1},{1,0,2,-1,-1,-1},{4,0,3,-1,-1,-1},{1,4,2,1,3,4},
    {3,1,5,-1,-1,-1},{2,3,0,2,5,3},{1,4,0,1,5,4},{4,2,5,-1,-1,-1},
    {4,5,2,-1,-1,-1},{4,1,0,4,5,1},{3,2,0,3,5,2},{1,3,5,-1,-1,-1},
    {4,1,2,4,3,1},{3,0,4,-1,-1,-1},{2,0,1,-1,-1,-1},{-1,-1,-1,-1,-1,-1}};
__device__ const int c_TET[16][12] = {
    {-1,-1,-1,-1,-1,-1,-1,-1,-1,-1,-1,-1},{0,4,5,6,-1,-1,-1,-1,-1,-1,-1,-1},
    {1,4,8,7,-1,-1,-1,-1,-1,-1,-1,-1},{7,1,8,6,5,1,7,6,5,0,1,6},
    {2,5,7,9,-1,-1,-1,-1,-1,-1,-1,-1},{4,0,6,7,9,0,7,6,7,0,9,2},
    {4,1,9,8,5,1,9,4,5,1,2,9},{6,0,1,2,8,6,1,2,9,6,8,2},
    {3,6,9,8,-1,-1,-1,-1,-1,-1,-1,-1},{5,0,4,8,5,0,8,3,5,8,9,3},
    {1,4,7,3,4,7,6,3,9,6,7,3},{0,1,5,3,5,1,9,3,5,1,7,9},
    {5,2,3,7,3,6,5,8,3,5,7,8},{0,4,7,8,0,3,8,7,0,3,7,2},
    {4,1,2,3,4,3,2,5,4,3,5,6},{0,1,2,3,-1,-1,-1,-1,-1,-1,-1,-1}};

// ---- scratch (static device memory; no runtime allocation) ----
__device__ unsigned int g_occbits[NWORDS];
__device__ unsigned char g_ti[MAXF];
__device__ int g_bcnt[MAXN];
__device__ int g_bstart[MAXN];             // after scatter: bucket END
__device__ unsigned long long g_bdata[MAXS];
__device__ int g_idxmap[MAXS];
__device__ int g_crossCnt[MAXN];
__device__ int g_crossX[MAXN];
__device__ int g_allTets[MAXTE];
__device__ unsigned char g_present[PRESCAP];
__device__ int g_presX[PRESCAP];
__device__ int g_bsums[NBLK_MAX];
__device__ ulonglong2 g_bsumsP[NB256 + 2];  // per-256-block cls sums / prefixes
// meta: 0 NT1  1 NT2  2 NTT1  3 INNER  4 E  5 U
//       6 facesOff(3E)  7 trows  8 vtOff  9 tetsOff  10 scratch
__device__ int g_meta[16];

__device__ __forceinline__ int occ_of(int v) {
    return (g_occbits[v >> 5] >> (v & 31)) & 1;
}

__device__ __forceinline__ unsigned long long pack16(int t) {
    return (unsigned long long)((M_NTRI1 >> t) & 1)
         | ((unsigned long long)((M_NTRI2 >> t) & 1) << 16)
         | ((unsigned long long)((M_NTET1 >> t) & 1) << 32)
         | ((unsigned long long)(t == 15 ? 1 : 0) << 48);
}

// Block-wide (256-thread) exclusive prefix over packed cls counters, plus the
// global per-block base from g_bsumsP. Every thread of the block must call.
__device__ __forceinline__ int4 cls_block_prefix(int t) {
    __shared__ unsigned long long sw[8];
    int lane = threadIdx.x & 31, wid = threadIdx.x >> 5;
    unsigned long long v = pack16(t);
    unsigned long long inc = v;
#pragma unroll
    for (int o = 1; o < 32; o <<= 1) {
        unsigned long long u = __shfl_up_sync(0xffffffffu, inc, o);
        if (lane >= o) inc += u;
    }
    if (lane == 31) sw[wid] = inc;
    __syncthreads();
    if (threadIdx.x == 0) {
        unsigned long long run = 0;
        for (int i = 0; i < 8; i++) { unsigned long long tmp = sw[i]; sw[i] = run; run += tmp; }
    }
    __syncthreads();
    unsigned long long ex = sw[wid] + inc - v;
    ulonglong2 bb = g_bsumsP[blockIdx.x];
    int4 r;
    r.x = (int)(ex & 0xffff) + (int)(bb.x & 0xffffffffULL);
    r.y = (int)((ex >> 16) & 0xffff) + (int)(bb.x >> 32);
    r.z = (int)((ex >> 32) & 0xffff) + (int)(bb.y & 0xffffffffULL);
    r.w = (int)((ex >> 48) & 0xffff) + (int)(bb.y >> 32);
    return r;
}

// 32-lane bitonic sort over u32 keys, registers + shfl_xor.
__device__ __forceinline__ unsigned warp_bitonic_u32(unsigned key, int lane) {
#pragma unroll
    for (int k = 2; k <= 32; k <<= 1) {
#pragma unroll
        for (int j = k >> 1; j > 0; j >>= 1) {
            unsigned other = __shfl_xor_sync(0xffffffffu, key, j);
            bool keepMin = (((lane & k) == 0) == ((lane & j) == 0));
            unsigned mn = key < other ? key : other;
            unsigned mx = key < other ? other : key;
            key = keepMin ? mn : mx;
        }
    }
    return key;
}

// ---------------------------------------------------------------------------
// scans
// ---------------------------------------------------------------------------
__global__ void k_scan_partial_int(const int* in, int n, int* bsums) {
    __shared__ int sh[256];
    int b = blockIdx.x, tid = threadIdx.x;
    int base = b * 2048 + tid * 8;
    int s = 0;
#pragma unroll
    for (int j = 0; j < 8; j++) { int i = base + j; if (i < n) s += in[i]; }
    sh[tid] = s; __syncthreads();
    for (int o = 128; o > 0; o >>= 1) { if (tid < o) sh[tid] += sh[tid + o]; __syncthreads(); }
    if (tid == 0) bsums[b] = sh[0];
}

// metaMode: 0 none, 1 crossCnt total (E + derived offsets), 2 presence total (U + tetsOff)
__global__ void k_scan_single(int* bsums, int nb, int metaMode) {
    __shared__ int sh[1024];
    int tid = threadIdx.x;
    int carry = 0;
    for (int base = 0; base < nb; base += 1024) {
        int i = base + tid;
        int v = (i < nb) ? bsums[i] : 0;
        sh[tid] = v; __syncthreads();
        for (int o = 1; o < 1024; o <<= 1) {
            int t = (tid >= o) ? sh[tid - o] : 0;
            __syncthreads(); sh[tid] += t; __syncthreads();
        }
        if (i < nb) bsums[i] = carry + sh[tid] - v;
        int tot = sh[1023]; __syncthreads();
        carry += tot;
    }
    if (tid == 0) {
        if (metaMode == 1) {
            int E = carry;
            int NT1 = g_meta[0], NT2 = g_meta[1], NTT1 = g_meta[2], INNER = g_meta[3];
            int NTT3 = NT1 + NT2 - NTT1;
            g_meta[4] = E;
            g_meta[6] = 3 * E;
            g_meta[7] = NTT1 + 3 * NTT3 + INNER;
            g_meta[8] = 3 * E + 3 * (NT1 + 2 * NT2);
        } else if (metaMode == 2) {
            g_meta[5] = carry;
            g_meta[9] = g_meta[8] + 3 * carry;
        }
    }
}

__global__ void k_scan_final_int(const int* in, int n, const int* bsums, int* outp) {
    __shared__ int sh[256];
    int b = blockIdx.x, tid = threadIdx.x;
    int base = b * 2048 + tid * 8;
    int v[8]; int s = 0;
#pragma unroll
    for (int j = 0; j < 8; j++) { int i = base + j; v[j] = (i < n) ? in[i] : 0; s += v[j]; }
    sh[tid] = s; __syncthreads();
    for (int o = 1; o < 256; o <<= 1) {
        int t = (tid >= o) ? sh[tid - o] : 0;
        __syncthreads(); sh[tid] += t; __syncthreads();
    }
    int run = bsums[b] + sh[tid] - s;
#pragma unroll
    for (int j = 0; j < 8; j++) { int i = base + j; if (i < n) outp[i] = run; run += v[j]; }
}

// dynamic-n u8 scans over g_present, n = N + E (E from g_meta[4])
__global__ void k_scan_partial_u8d(int N, int* bsums) {
    __shared__ int sh[256];
    int n = N + g_meta[4];
    int b = blockIdx.x, tid = threadIdx.x;
    long long base = (long long)b * 2048 + tid * 8;
    int s = 0;
    if (base + 8 <= n) {
        unsigned long long v = *(const unsigned long long*)(g_present + base);
        s = __popcll(v);                    // bytes are 0/1
    } else {
        for (int j = 0; j < 8; j++) { long long i = base + j; if (i < n) s += g_present[i]; }
    }
    sh[tid] = s; __syncthreads();
    for (int o = 128; o > 0; o >>= 1) { if (tid < o) sh[tid] += sh[tid + o]; __syncthreads(); }
    if (tid == 0) bsums[b] = sh[0];
}

__global__ void k_scan_final_u8d(int N, const int* bsums) {
    __shared__ int sh[256];
    int n = N + g_meta[4];
    int b = blockIdx.x, tid = threadIdx.x;
    long long base = (long long)b * 2048 + tid * 8;
    int v[8]; int s = 0;
    if (base + 8 <= n) {
        unsigned long long vv = *(const unsigned long long*)(g_present + base);
#pragma unroll
        for (int j = 0; j < 8; j++) { v[j] = (int)((vv >> (8 * j)) & 0xff); s += v[j]; }
    } else {
#pragma unroll
        for (int j = 0; j < 8; j++) { long long i = base + j; v[j] = (i < n) ? (int)g_present[i] : 0; s += v[j]; }
    }
    sh[tid] = s; __syncthreads();
    for (int o = 1; o < 256; o <<= 1) {
        int t = (tid >= o) ? sh[tid - o] : 0;
        __syncthreads(); sh[tid] += t; __syncthreads();
    }
    int run = bsums[b] + sh[tid] - s;
#pragma unroll
    for (int j = 0; j < 8; j++) { long long i = base + j; if (i < n) g_presX[i] = run; run += v[j]; }
}

// single-block scan over packed per-block cls sums (2 u64 components)
__global__ void k_scan_singleP(int nb) {
    __shared__ unsigned long long sh[1024];
    unsigned long long* bs = (unsigned long long*)g_bsumsP;
    int tid = threadIdx.x;
    for (int c = 0; c < 2; c++) {
        unsigned long long carry = 0;
        for (int base = 0; base < nb; base += 1024) {
            int i = base + tid;
            unsigned long long v = (i < nb) ? bs[i * 2 + c] : 0;
            sh[tid] = v; __syncthreads();
            for (int o = 1; o < 1024; o <<= 1) {
                unsigned long long t = (tid >= o) ? sh[tid - o] : 0;
                __syncthreads(); sh[tid] += t; __syncthreads();
            }
            if (i < nb) bs[i * 2 + c] = carry + sh[tid] - v;
            unsigned long long tot = sh[1023]; __syncthreads();
            carry += tot;
        }
        if (tid == 0) {
            if (c == 0) { g_meta[0] = (int)(carry & 0xffffffffULL); g_meta[1] = (int)(carry >> 32); }
            else        { g_meta[2] = (int)(carry & 0xffffffffULL); g_meta[3] = (int)(carry >> 32); }
        }
        __syncthreads();
    }
}

// ---------------------------------------------------------------------------
// pipeline kernels
// ---------------------------------------------------------------------------
__global__ void k_occbits(const float* sdf, const float* th, int N, int NW) {
    int i = blockIdx.x * blockDim.x + threadIdx.x;
    float t = th[0];
    bool p = false;
    if (i < N) { float s = sdf[i]; p = (s > 0.f && s <= t); }
    unsigned m = __ballot_sync(0xffffffffu, p);
    if ((threadIdx.x & 31) == 0 && (i >> 5) < NW) g_occbits[i >> 5] = m;
    if (i < N) g_bcnt[i] = 0;      // fused bucket-count reset
}

// tetindex + per-bucket edge counts + per-block packed cls sums (one tet pass)
__global__ void k_ti_count(const int4* tet, int F) {
    __shared__ unsigned long long sw[8];
    int f = blockIdx.x * 256 + threadIdx.x;
    int lane = threadIdx.x & 31, wid = threadIdx.x >> 5;
    int t = 0;
    if (f < F) {
        int4 q = tet[f];
        t = occ_of(q.x) | (occ_of(q.y) << 1) | (occ_of(q.z) << 2) | (occ_of(q.w) << 3);
        g_ti[f] = (unsigned char)t;
        if (t != 0 && t != 15) {
            int qq[4] = {q.x, q.y, q.z, q.w};
#pragma unroll
            for (int k = 0; k < 6; k++) {
                int a = qq[c_BE[2 * k]], b = qq[c_BE[2 * k + 1]];
                atomicAdd(&g_bcnt[a < b ? a : b], 1);
            }
        }
    }
    unsigned long long v = pack16(t);
#pragma unroll
    for (int o = 16; o > 0; o >>= 1) v += __shfl_down_sync(0xffffffffu, v, o);
    if (lane == 0) sw[wid] = v;
    __syncthreads();
    if (threadIdx.x == 0) {
        unsigned long long tot = 0;
        for (int i = 0; i < 8; i++) tot += sw[i];
        ulonglong2 r;
        r.x = (tot & 0xffffULL) | (((tot >> 16) & 0xffffULL) << 32);
        r.y = ((tot >> 32) & 0xffffULL) | (((tot >> 48) & 0xffffULL) << 32);
        g_bsumsP[blockIdx.x] = r;
    }
}

__global__ void k_scatter(const int4* tet, int F) {
    int f = blockIdx.x * 256 + threadIdx.x;
    int t = (f < F) ? (int)g_ti[f] : 0;
    int4 pre = cls_block_prefix(t);
    if (f >= F || t == 0 || t == 15) return;
    int r = pre.x + pre.y;          // valid-tet rank
    int4 q = tet[f];
    int qq[4] = {q.x, q.y, q.z, q.w};
#pragma unroll
    for (int k = 0; k < 6; k++) {
        int a = qq[c_BE[2 * k]], b = qq[c_BE[2 * k + 1]];
        int lo = a < b ? a : b, hi = a < b ? b : a;
        int pos = atomicAdd(&g_bstart[lo], 1);
        g_bdata[pos] = ((unsigned long long)(unsigned)hi << 32) | (unsigned)(r * 6 + k);
    }
}

// Phase 1: distinct crossing count per bucket — no sort, match_any + ballot.
__global__ void k_bcount(int N) {
    int lane = threadIdx.x & 31;
    int b = (blockIdx.x * blockDim.x + threadIdx.x) >> 5;
    if (b >= N) return;
    int n = g_bcnt[b];
    if (n == 0) { if (lane == 0) g_crossCnt[b] = 0; return; }
    long long s = (long long)g_bstart[b] - n;   // bstart holds bucket END
    int occa = occ_of(b);
    if (n <= 32) {
        int hi = -1;
        if (lane < n) hi = (int)(g_bdata[s + lane] >> 32);
        unsigned peers = __match_any_sync(0xffffffffu, hi);
        bool leader = (lane < n) && (lane == __ffs(peers) - 1);
        bool cross = leader && ((occa ^ occ_of(hi)) != 0);
        int c = __popc(__ballot_sync(0xffffffffu, cross));
        if (lane == 0) g_crossCnt[b] = c;
    } else if (lane == 0) {
        // rare fallback: in-place sort (leaves g_bdata sorted for k_bemit)
        for (int i = 1; i < n; i++) {
            unsigned long long key = g_bdata[s + i];
            int j = i - 1;
            while (j >= 0 && g_bdata[s + j] > key) { g_bdata[s + j + 1] = g_bdata[s + j]; j--; }
            g_bdata[s + j + 1] = key;
        }
        long long prev = -1; int c = 0;
        for (int i = 0; i < n; i++) {
            int hv = (int)(g_bdata[s + i] >> 32);
            if (hv != prev) { c += occa ^ occ_of(hv); prev = hv; }
        }
        g_crossCnt[b] = c;
    }
}

// Phase 2: 32-bit register sort for ranking, shfl binary search for mapping,
// idxmap writes + interpolated vertex emission (fused).
__global__ void k_bemit(const float* pos, const float* sdf, const float* th,
                        float* out, int N) {
    int lane = threadIdx.x & 31;
    int b = (blockIdx.x * blockDim.x + threadIdx.x) >> 5;
    if (b >= N) return;
    int n = g_bcnt[b];
    if (n == 0) return;
    long long s = (long long)g_bstart[b] - n;
    int base = g_crossX[b];
    int occa = occ_of(b);
    if (n <= 32) {
        unsigned key = 0xffffffffu;
        int slot = 0;
        if (lane < n) {
            unsigned long long d = g_bdata[s + lane];
            key = (unsigned)(d >> 32);
            slot = (int)(d & 0xffffffffu);
        }
        unsigned sk = warp_bitonic_u32(key, lane);
        unsigned sprev = __shfl_up_sync(0xffffffffu, sk, 1);
        bool valid = (sk != 0xffffffffu);
        bool srep = valid && (lane == 0 || sprev != sk);
        bool scross = srep && ((occa ^ occ_of((int)sk)) != 0);
        unsigned crossB = __ballot_sync(0xffffffffu, scross);
        int rank = __popc(crossB & ((1u << lane) - 1u));
        int seid = scross ? (base + rank) : -1;
        // each unsorted lane: lower-bound binary search into sorted regs
        int p = 0;
#pragma unroll
        for (int st = 16; st >= 1; st >>= 1) {
            unsigned v = __shfl_sync(0xffffffffu, sk, p + st - 1);
            if (v < key) p += st;
        }
        int mv = __shfl_sync(0xffffffffu, seid, p);
        if (lane < n) g_idxmap[slot] = mv;
        if (scross) {
            int hv = (int)sk;
            float t = th[0];
            float s0 = sdf[b], s1 = sdf[hv];
            if (s0 > 0.f && s1 > 0.f) { s0 -= t; s1 -= t; }
            float inv = 1.f / (s0 - s1);
            float w0 = -s1 * inv, w1 = s0 * inv;
#pragma unroll
            for (int c = 0; c < 3; c++)
                out[seid * 3 + c] = pos[b * 3 + c] * w0 + pos[hv * 3 + c] * w1;
        }
    } else if (lane == 0) {
        // fallback: g_bdata already sorted by k_bcount
        long long prev = -1; int c = 0, mv = -1;
        for (int i = 0; i < n; i++) {
            unsigned long long d = g_bdata[s + i];
            int hv = (int)(d >> 32);
            int slot = (int)(d & 0xffffffffu);
            if (hv != prev) {
                if (occa ^ occ_of(hv)) {
                    int eid = base + c;
                    float t = th[0];
                    float s0 = sdf[b], s1 = sdf[hv];
                    if (s0 > 0.f && s1 > 0.f) { s0 -= t; s1 -= t; }
                    float inv = 1.f / (s0 - s1);
                    float w0 = -s1 * inv, w1 = s0 * inv;
                    for (int cc = 0; cc < 3; cc++)
                        out[eid * 3 + cc] = pos[b * 3 + cc] * w0 + pos[hv * 3 + cc] * w1;
                    mv = eid; c++;
                } else mv = -1;
                prev = hv;
            }
            g_idxmap[slot] = mv;
        }
    }
}

__global__ void k_fill_present(int N) {
    int n2 = N + g_meta[4];
    int nw = (n2 + 3) >> 2;
    int i = blockIdx.x * blockDim.x + threadIdx.x;
    if (i < nw) ((int*)g_present)[i] = 0;
}

// fused: faces emission + tetmesh connectivity build + presence marking
__global__ void k_emit(const int4* tet, float* out, int F, int N) {
    int f = blockIdx.x * 256 + threadIdx.x;
    int t = (f < F) ? (int)g_ti[f] : 0;
    int4 cls = cls_block_prefix(t);
    if (f >= F || t == 0) return;
    int4 q = tet[f];
    int qq[4] = {q.x, q.y, q.z, q.w};
    if (t == 15) {
        int NTT3 = g_meta[0] + g_meta[1] - g_meta[2];
        int row = g_meta[2] + 3 * NTT3 + cls.w;
#pragma unroll
        for (int j = 0; j < 4; j++) {
            g_allTets[row * 4 + j] = qq[j];
            g_present[qq[j]] = 1;
        }
        return;
    }
    int r = cls.x + cls.y;          // valid-tet rank
    int foff = g_meta[6];
    if ((M_NTRI1 >> t) & 1) {
        int row = cls.x;
#pragma unroll
        for (int j = 0; j < 3; j++)
            out[foff + row * 3 + j] = (float)g_idxmap[r * 6 + c_TRI[t][j]];
    } else {
        int row = g_meta[0] + 2 * cls.y;
#pragma unroll
        for (int j = 0; j < 6; j++)
            out[foff + row * 3 + j] = (float)g_idxmap[r * 6 + c_TRI[t][j]];
    }
    if ((M_NTET1 >> t) & 1) {
        int row = cls.z;
#pragma unroll
        for (int j = 0; j < 4; j++) {
            int e = c_TET[t][j];
            int val = (e < 4) ? qq[e] : (g_idxmap[r * 6 + e - 4] + N);
            g_allTets[row * 4 + j] = val;
            g_present[val] = 1;
        }
    } else {
        int row = g_meta[2] + 3 * (r - cls.z);
#pragma unroll
        for (int m = 0; m < 12; m++) {
            int e = c_TET[t][m];
            int val = (e < 4) ? qq[e] : (g_idxmap[r * 6 + e - 4] + N);
            g_allTets[row * 4 + m] = val;
            g_present[val] = 1;
        }
    }
}

__global__ void k_vt(const float* pos, float* out, int N) {
    int n2 = N + g_meta[4];
    int idx = blockIdx.x * blockDim.x + threadIdx.x;
    if (idx >= n2) return;
    if (!g_present[idx]) return;
    int uid = g_presX[idx];
    float x, y, z;
    if (idx < N) {
        x = pos[idx * 3 + 0]; y = pos[idx * 3 + 1]; z = pos[idx * 3 + 2];
    } else {
        int e = idx - N;
        x = out[e * 3 + 0]; y = out[e * 3 + 1]; z = out[e * 3 + 2];
    }
    int o = g_meta[8];
    out[o + uid * 3 + 0] = x;
    out[o + uid * 3 + 1] = y;
    out[o + uid * 3 + 2] = z;
}

__global__ void k_tout(float* out) {
    int i = blockIdx.x * blockDim.x + threadIdx.x;
    if (i >= 4 * g_meta[7]) return;
    out[g_meta[9] + i] = (float)g_presX[g_allTets[i]];
}

// ---------------------------------------------------------------------------
// host launcher
// ---------------------------------------------------------------------------
static inline int gb(long long n) { return (int)((n + 255) / 256); }

extern "C" void kernel_launch(void* const* d_in, const int* in_sizes, int n_in,
                              void* d_out, int out_size) {
    const float* pos = (const float*)d_in[0];
    const float* sdf = (const float*)d_in[1];
    const int4* tet = (const int4*)d_in[2];
    const float* thick = (const float*)d_in[3];
    float* out = (float*)d_out;

    int N = in_sizes[1];
    int F = in_sizes[2] / 4;
    if (N > MAXN) N = MAXN;
    if (F > MAXF) F = MAXF;
    int NW = (N + 31) / 32;
    int PL = N + MAXS;

    int *p_bcnt, *p_bstart, *p_crossCnt, *p_crossX, *p_bsums;
    cudaGetSymbolAddress((void**)&p_bcnt, g_bcnt);
    cudaGetSymbolAddress((void**)&p_bstart, g_bstart);
    cudaGetSymbolAddress((void**)&p_crossCnt, g_crossCnt);
    cudaGetSymbolAddress((void**)&p_crossX, g_crossX);
    cudaGetSymbolAddress((void**)&p_bsums, g_bsums);

    int nbF = (F + 255) / 256;          // cls blocks
    int nbN = (N + 2047) / 2048;        // N-domain scan blocks
    int nbP = (PL + 2047) / 2048;       // presence scan blocks (worst case)

    // 1. occupancy bitmask (+bcnt reset), then tetindex + counts + cls block sums
    k_occbits<<<gb((long long)NW * 32), 256>>>(sdf, thick, N, NW);
    k_ti_count<<<nbF, 256>>>(tet, F);
    k_scan_singleP<<<1, 1024>>>(nbF);   // -> per-block cls bases + meta[0..3]

    // 2. bucket offsets + edge scatter (bstart becomes bucket end)
    k_scan_partial_int<<<nbN, 256>>>(p_bcnt, N, p_bsums);
    k_scan_single<<<1, 1024>>>(p_bsums, nbN, 0);
    k_scan_final_int<<<nbN, 256>>>(p_bcnt, N, p_bsums, p_bstart);
    k_scatter<<<nbF, 256>>>(tet, F);

    // 3. crossing counts (match_any, no sort) -> prefix -> assignment + verts
    k_bcount<<<gb((long long)N * 32), 256>>>(N);
    k_scan_partial_int<<<nbN, 256>>>(p_crossCnt, N, p_bsums);
    k_scan_single<<<1, 1024>>>(p_bsums, nbN, 1);   // sets E + offsets
    k_scan_final_int<<<nbN, 256>>>(p_crossCnt, N, p_bsums, p_crossX);
    k_bemit<<<gb((long long)N * 32), 256>>>(pos, sdf, thick, out, N);

    // 4. presence reset over [0, N+E) then faces + tets + marks (fused)
    k_fill_present<<<gb(PL / 4), 256>>>(N);
    k_emit<<<nbF, 256>>>(tet, out, F, N);

    // 5. presence scan over [0, N+E) -> sorted-unique ids (+U, tetsOff)
    k_scan_partial_u8d<<<nbP, 256>>>(N, p_bsums);
    k_scan_single<<<1, 1024>>>(p_bsums, nbP, 2);
    k_scan_final_u8d<<<nbP, 256>>>(N, p_bsums);

    // 6. verts_tetmesh (region 2) + tets_tetmesh (region 3)
    k_vt<<<gb(PL), 256>>>(pos, out, N);
    k_tout<<<gb(MAXTE), 256>>>(out);
}

// round 8
// speedup vs baseline: 2.4829x; 1.4226x over previous
#include <cuda_runtime.h>
#include <cuda_bf16.h>
#include <cstdint>

// ---------------------------------------------------------------------------
// DMTet geometry, fully on-device. Outputs concatenated into d_out (float32):
//   [ verts (E*3) | faces (Fc*3) | verts_tetmesh (U*3) | tets_tetmesh (T*4) ]
// ---------------------------------------------------------------------------

#define MAXN 400000
#define MAXF 2000000
#define MAXS (6 * MAXF)            // max edge slots (6 per tet, slot = f*6+k)
#define MAXTE (12 * MAXF)          // max all_tets entries
#define PRESCAP (MAXN + MAXS)      // presence domain [0, N+E)
#define NBLK_MAX ((PRESCAP + 2047) / 2048 + 2)
#define NWORDS ((MAXN + 31) / 32)
#define NB256 ((MAXF + 255) / 256)
#define NBKT (2 * MAXN)            // buckets: (lo, hi-half) -> max lambda ~18
#define BROW 64                    // bucket row capacity; P(overflow) ~ 5e-17

// classification bitmasks over tetindex
#define M_NTRI1 0x6996             // ti with 1 triangle
#define M_NTRI2 0x1668             // ti with 2 triangles
#define M_NTET1 0x0116             // valid ti with 1 tet

__device__ const int c_BE[12] = {0,1,0,2,0,3,1,2,1,3,2,3};
__device__ const int c_TRI[16][6] = {
    {-1,-1,-1,-1,-1,-1},{1,0,2,-1,-1,-1},{4,0,3,-1,-1,-1},{1,4,2,1,3,4},
    {3,1,5,-1,-1,-1},{2,3,0,2,5,3},{1,4,0,1,5,4},{4,2,5,-1,-1,-1},
    {4,5,2,-1,-1,-1},{4,1,0,4,5,1},{3,2,0,3,5,2},{1,3,5,-1,-1,-1},
    {4,1,2,4,3,1},{3,0,4,-1,-1,-1},{2,0,1,-1,-1,-1},{-1,-1,-1,-1,-1,-1}};
__device__ const int c_TET[16][12] = {
    {-1,-1,-1,-1,-1,-1,-1,-1,-1,-1,-1,-1},{0,4,5,6,-1,-1,-1,-1,-1,-1,-1,-1},
    {1,4,8,7,-1,-1,-1,-1,-1,-1,-1,-1},{7,1,8,6,5,1,7,6,5,0,1,6},
    {2,5,7,9,-1,-1,-1,-1,-1,-1,-1,-1},{4,0,6,7,9,0,7,6,7,0,9,2},
    {4,1,9,8,5,1,9,4,5,1,2,9},{6,0,1,2,8,6,1,2,9,6,8,2},
    {3,6,9,8,-1,-1,-1,-1,-1,-1,-1,-1},{5,0,4,8,5,0,8,3,5,8,9,3},
    {1,4,7,3,4,7,6,3,9,6,7,3},{0,1,5,3,5,1,9,3,5,1,7,9},
    {5,2,3,7,3,6,5,8,3,5,7,8},{0,4,7,8,0,3,8,7,0,3,7,2},
    {4,1,2,3,4,3,2,5,4,3,5,6},{0,1,2,3,-1,-1,-1,-1,-1,-1,-1,-1}};

// ---- scratch (static device memory; no runtime allocation) ----
__device__ unsigned int g_occbits[NWORDS];
__device__ unsigned char g_ti[MAXF];
__device__ int g_bcnt[NBKT];
__device__ __align__(16) unsigned long long g_bdata[(long long)NBKT * BROW];
__device__ int g_idxmap[MAXS];
__device__ int g_crossCnt[NBKT];
__device__ int g_crossX[NBKT];
__device__ __align__(16) int g_allTets[MAXTE];
__device__ __align__(16) unsigned char g_present[PRESCAP];
__device__ int g_presX[PRESCAP];
__device__ int g_bsums[NBLK_MAX];
__device__ ulonglong2 g_bsumsP[NB256 + 2];  // per-256-block cls sums / prefixes
// meta: 0 NT1  1 NT2  2 NTT1  3 INNER  4 E  5 U
//       6 facesOff(3E)  7 trows  8 vtOff  9 tetsOff
__device__ int g_meta[16];

__device__ __forceinline__ int occ_of(int v) {
    return (g_occbits[v >> 5] >> (v & 31)) & 1;
}

__device__ __forceinline__ unsigned long long pack16(int t) {
    return (unsigned long long)((M_NTRI1 >> t) & 1)
         | ((unsigned long long)((M_NTRI2 >> t) & 1) << 16)
         | ((unsigned long long)((M_NTET1 >> t) & 1) << 32)
         | ((unsigned long long)(t == 15 ? 1 : 0) << 48);
}

// Block-wide (256-thread) exclusive prefix over packed cls counters, plus the
// global per-block base from g_bsumsP. Every thread of the block must call.
__device__ __forceinline__ int4 cls_block_prefix(int t) {
    __shared__ unsigned long long sw[8];
    int lane = threadIdx.x & 31, wid = threadIdx.x >> 5;
    unsigned long long v = pack16(t);
    unsigned long long inc = v;
#pragma unroll
    for (int o = 1; o < 32; o <<= 1) {
        unsigned long long u = __shfl_up_sync(0xffffffffu, inc, o);
        if (lane >= o) inc += u;
    }
    if (lane == 31) sw[wid] = inc;
    __syncthreads();
    if (threadIdx.x == 0) {
        unsigned long long run = 0;
        for (int i = 0; i < 8; i++) { unsigned long long tmp = sw[i]; sw[i] = run; run += tmp; }
    }
    __syncthreads();
    unsigned long long ex = sw[wid] + inc - v;
    ulonglong2 bb = g_bsumsP[blockIdx.x];
    int4 r;
    r.x = (int)(ex & 0xffff) + (int)(bb.x & 0xffffffffULL);
    r.y = (int)((ex >> 16) & 0xffff) + (int)(bb.x >> 32);
    r.z = (int)((ex >> 32) & 0xffff) + (int)(bb.y & 0xffffffffULL);
    r.w = (int)((ex >> 48) & 0xffff) + (int)(bb.y >> 32);
    return r;
}

// 32-lane bitonic sort over u32 keys, registers + shfl_xor.
__device__ __forceinline__ unsigned warp_bitonic_u32(unsigned key, int lane) {
#pragma unroll
    for (int k = 2; k <= 32; k <<= 1) {
#pragma unroll
        for (int j = k >> 1; j > 0; j >>= 1) {
            unsigned other = __shfl_xor_sync(0xffffffffu, key, j);
            bool keepMin = (((lane & k) == 0) == ((lane & j) == 0));
            unsigned mn = key < other ? key : other;
            unsigned mx = key < other ? other : key;
            key = keepMin ? mn : mx;
        }
    }
    return key;
}

// ---------------------------------------------------------------------------
// scans
// ---------------------------------------------------------------------------
__global__ void k_scan_partial_int(const int* in, int n, int* bsums) {
    __shared__ int sh[256];
    int b = blockIdx.x, tid = threadIdx.x;
    int base = b * 2048 + tid * 8;
    int s = 0;
#pragma unroll
    for (int j = 0; j < 8; j++) { int i = base + j; if (i < n) s += in[i]; }
    sh[tid] = s; __syncthreads();
    for (int o = 128; o > 0; o >>= 1) { if (tid < o) sh[tid] += sh[tid + o]; __syncthreads(); }
    if (tid == 0) bsums[b] = sh[0];
}

// metaMode: 1 crossCnt total (E + derived offsets), 2 presence total (U + tetsOff)
__global__ void k_scan_single(int* bsums, int nb, int metaMode) {
    __shared__ int sh[1024];
    int tid = threadIdx.x;
    int carry = 0;
    for (int base = 0; base < nb; base += 1024) {
        int i = base + tid;
        int v = (i < nb) ? bsums[i] : 0;
        sh[tid] = v; __syncthreads();
        for (int o = 1; o < 1024; o <<= 1) {
            int t = (tid >= o) ? sh[tid - o] : 0;
            __syncthreads(); sh[tid] += t; __syncthreads();
        }
        if (i < nb) bsums[i] = carry + sh[tid] - v;
        int tot = sh[1023]; __syncthreads();
        carry += tot;
    }
    if (tid == 0) {
        if (metaMode == 1) {
            int E = carry;
            int NT1 = g_meta[0], NT2 = g_meta[1], NTT1 = g_meta[2], INNER = g_meta[3];
            int NTT3 = NT1 + NT2 - NTT1;
            g_meta[4] = E;
            g_meta[6] = 3 * E;
            g_meta[7] = NTT1 + 3 * NTT3 + INNER;
            g_meta[8] = 3 * E + 3 * (NT1 + 2 * NT2);
        } else if (metaMode == 2) {
            g_meta[5] = carry;
            g_meta[9] = g_meta[8] + 3 * carry;
        }
    }
}

__global__ void k_scan_final_int(const int* in, int n, const int* bsums, int* outp) {
    __shared__ int sh[256];
    int b = blockIdx.x, tid = threadIdx.x;
    int base = b * 2048 + tid * 8;
    int v[8]; int s = 0;
#pragma unroll
    for (int j = 0; j < 8; j++) { int i = base + j; v[j] = (i < n) ? in[i] : 0; s += v[j]; }
    sh[tid] = s; __syncthreads();
    for (int o = 1; o < 256; o <<= 1) {
        int t = (tid >= o) ? sh[tid - o] : 0;
        __syncthreads(); sh[tid] += t; __syncthreads();
    }
    int run = bsums[b] + sh[tid] - s;
#pragma unroll
    for (int j = 0; j < 8; j++) { int i = base + j; if (i < n) outp[i] = run; run += v[j]; }
}

// dynamic-n u8 scans over g_present, n = N + E (E from g_meta[4])
__global__ void k_scan_partial_u8d(int N, int* bsums) {
    __shared__ int sh[256];
    int n = N + g_meta[4];
    int b = blockIdx.x, tid = threadIdx.x;
    long long base = (long long)b * 2048 + tid * 8;
    int s = 0;
    if (base + 8 <= n) {
        unsigned long long v = *(const unsigned long long*)(g_present + base);
        s = __popcll(v);                    // bytes are 0/1
    } else {
        for (int j = 0; j < 8; j++) { long long i = base + j; if (i < n) s += g_present[i]; }
    }
    sh[tid] = s; __syncthreads();
    for (int o = 128; o > 0; o >>= 1) { if (tid < o) sh[tid] += sh[tid + o]; __syncthreads(); }
    if (tid == 0) bsums[b] = sh[0];
}

__global__ void k_scan_final_u8d(int N, const int* bsums) {
    __shared__ int sh[256];
    int n = N + g_meta[4];
    int b = blockIdx.x, tid = threadIdx.x;
    long long base = (long long)b * 2048 + tid * 8;
    int v[8]; int s = 0;
    if (base + 8 <= n) {
        unsigned long long vv = *(const unsigned long long*)(g_present + base);
#pragma unroll
        for (int j = 0; j < 8; j++) { v[j] = (int)((vv >> (8 * j)) & 0xff); s += v[j]; }
    } else {
#pragma unroll
        for (int j = 0; j < 8; j++) { long long i = base + j; v[j] = (i < n) ? (int)g_present[i] : 0; s += v[j]; }
    }
    sh[tid] = s; __syncthreads();
    for (int o = 1; o < 256; o <<= 1) {
        int t = (tid >= o) ? sh[tid - o] : 0;
        __syncthreads(); sh[tid] += t; __syncthreads();
    }
    int run = bsums[b] + sh[tid] - s;
#pragma unroll
    for (int j = 0; j < 8; j++) { long long i = base + j; if (i < n) g_presX[i] = run; run += v[j]; }
}

// single-block scan over packed per-block cls sums (2 u64 components)
__global__ void k_scan_singleP(int nb) {
    __shared__ unsigned long long sh[1024];
    unsigned long long* bs = (unsigned long long*)g_bsumsP;
    int tid = threadIdx.x;
    for (int c = 0; c < 2; c++) {
        unsigned long long carry = 0;
        for (int base = 0; base < nb; base += 1024) {
            int i = base + tid;
            unsigned long long v = (i < nb) ? bs[i * 2 + c] : 0;
            sh[tid] = v; __syncthreads();
            for (int o = 1; o < 1024; o <<= 1) {
                unsigned long long t = (tid >= o) ? sh[tid - o] : 0;
                __syncthreads(); sh[tid] += t; __syncthreads();
            }
            if (i < nb) bs[i * 2 + c] = carry + sh[tid] - v;
            unsigned long long tot = sh[1023]; __syncthreads();
            carry += tot;
        }
        if (tid == 0) {
            if (c == 0) { g_meta[0] = (int)(carry & 0xffffffffULL); g_meta[1] = (int)(carry >> 32); }
            else        { g_meta[2] = (int)(carry & 0xffffffffULL); g_meta[3] = (int)(carry >> 32); }
        }
        __syncthreads();
    }
}

// ---------------------------------------------------------------------------
// pipeline kernels
// ---------------------------------------------------------------------------
__global__ void k_occbits(const float* sdf, const float* th, int N, int NW) {
    int i = blockIdx.x * blockDim.x + threadIdx.x;
    float t = th[0];
    bool p = false;
    if (i < N) { float s = sdf[i]; p = (s > 0.f && s <= t); }
    unsigned m = __ballot_sync(0xffffffffu, p);
    if ((threadIdx.x & 31) == 0 && (i >> 5) < NW) g_occbits[i >> 5] = m;
    if (i < N) {                    // fused bucket-count reset (2 buckets per vertex)
        g_bcnt[2 * i] = 0;
        g_bcnt[2 * i + 1] = 0;
    }
}

// One tet pass: tetindex + per-block packed cls sums + direct edge scatter
// into the fixed-stride bucket matrix. Bucket = lo*2 + (hi >= NHALF) to cap
// the skewed per-lo load (lambda <= ~18 per bucket). Slot id = f*6+k.
__global__ void k_ti_scatter(const int4* tet, int F, int NHALF) {
    __shared__ unsigned long long sw[8];
    int f = blockIdx.x * 256 + threadIdx.x;
    int lane = threadIdx.x & 31, wid = threadIdx.x >> 5;
    int t = 0;
    if (f < F) {
        int4 q = tet[f];
        t = occ_of(q.x) | (occ_of(q.y) << 1) | (occ_of(q.z) << 2) | (occ_of(q.w) << 3);
        g_ti[f] = (unsigned char)t;
        if (t != 0 && t != 15) {
            int qq[4] = {q.x, q.y, q.z, q.w};
#pragma unroll
            for (int k = 0; k < 6; k++) {
                int a = qq[c_BE[2 * k]], b = qq[c_BE[2 * k + 1]];
                int lo = a < b ? a : b, hi = a < b ? b : a;
                int bkt = (lo << 1) | (hi >= NHALF ? 1 : 0);
                int idx = atomicAdd(&g_bcnt[bkt], 1);
                if (idx < BROW)
                    g_bdata[(long long)bkt * BROW + idx] =
                        ((unsigned long long)(unsigned)hi << 32) | (unsigned)(f * 6 + k);
            }
        }
    }
    unsigned long long v = pack16(t);
#pragma unroll
    for (int o = 16; o > 0; o >>= 1) v += __shfl_down_sync(0xffffffffu, v, o);
    if (lane == 0) sw[wid] = v;
    __syncthreads();
    if (threadIdx.x == 0) {
        unsigned long long tot = 0;
        for (int i = 0; i < 8; i++) tot += sw[i];
        ulonglong2 r;
        r.x = (tot & 0xffffULL) | (((tot >> 16) & 0xffffULL) << 32);
        r.y = ((tot >> 32) & 0xffffULL) | (((tot >> 48) & 0xffffULL) << 32);
        g_bsumsP[blockIdx.x] = r;
    }
}

// Phase 1: distinct crossing count per bucket — no sort, match_any + ballot.
__global__ void k_bcount(int NB) {
    int lane = threadIdx.x & 31;
    int b = (blockIdx.x * blockDim.x + threadIdx.x) >> 5;
    if (b >= NB) return;
    int n = min(g_bcnt[b], BROW);
    if (n == 0) { if (lane == 0) g_crossCnt[b] = 0; return; }
    long long s = (long long)b * BROW;
    int occa = occ_of(b >> 1);
    if (n <= 32) {
        int hi = -1;
        if (lane < n) hi = (int)(g_bdata[s + lane] >> 32);
        unsigned peers = __match_any_sync(0xffffffffu, hi);
        bool leader = (lane < n) && (lane == __ffs(peers) - 1);
        bool cross = leader && ((occa ^ occ_of(hi)) != 0);
        int c = __popc(__ballot_sync(0xffffffffu, cross));
        if (lane == 0) g_crossCnt[b] = c;
    } else if (lane == 0) {
        // rare fallback: in-place sort (leaves row sorted for k_bemit)
        for (int i = 1; i < n; i++) {
            unsigned long long key = g_bdata[s + i];
            int j = i - 1;
            while (j >= 0 && g_bdata[s + j] > key) { g_bdata[s + j + 1] = g_bdata[s + j]; j--; }
            g_bdata[s + j + 1] = key;
        }
        long long prev = -1; int c = 0;
        for (int i = 0; i < n; i++) {
            int hv = (int)(g_bdata[s + i] >> 32);
            if (hv != prev) { c += occa ^ occ_of(hv); prev = hv; }
        }
        g_crossCnt[b] = c;
    }
}

// Phase 2: 32-bit register sort for ranking, shfl binary search for mapping,
// idxmap writes + interpolated vertex emission (fused).
__global__ void k_bemit(const float* pos, const float* sdf, const float* th,
                        float* out, int NB) {
    int lane = threadIdx.x & 31;
    int b = (blockIdx.x * blockDim.x + threadIdx.x) >> 5;
    if (b >= NB) return;
    int n = min(g_bcnt[b], BROW);
    if (n == 0) return;
    long long s = (long long)b * BROW;
    int base = g_crossX[b];
    int lo = b >> 1;
    int occa = occ_of(lo);
    if (n <= 32) {
        unsigned key = 0xffffffffu;
        int slot = 0;
        if (lane < n) {
            unsigned long long d = g_bdata[s + lane];
            key = (unsigned)(d >> 32);
            slot = (int)(d & 0xffffffffu);
        }
        unsigned sk = warp_bitonic_u32(key, lane);
        unsigned sprev = __shfl_up_sync(0xffffffffu, sk, 1);
        bool valid = (sk != 0xffffffffu);
        bool srep = valid && (lane == 0 || sprev != sk);
        bool scross = srep && ((occa ^ occ_of((int)sk)) != 0);
        unsigned crossB = __ballot_sync(0xffffffffu, scross);
        int rank = __popc(crossB & ((1u << lane) - 1u));
        int seid = scross ? (base + rank) : -1;
        // each unsorted lane: lower-bound binary search into sorted regs
        int p = 0;
#pragma unroll
        for (int st = 16; st >= 1; st >>= 1) {
            unsigned v = __shfl_sync(0xffffffffu, sk, p + st - 1);
            if (v < key) p += st;
        }
        int mv = __shfl_sync(0xffffffffu, seid, p);
        if (lane < n) g_idxmap[slot] = mv;
        if (scross) {
            int hv = (int)sk;
            float t = th[0];
            float s0 = sdf[lo], s1 = sdf[hv];
            if (s0 > 0.f && s1 > 0.f) { s0 -= t; s1 -= t; }
            float inv = 1.f / (s0 - s1);
            float w0 = -s1 * inv, w1 = s0 * inv;
#pragma unroll
            for (int c = 0; c < 3; c++)
                out[seid * 3 + c] = pos[lo * 3 + c] * w0 + pos[hv * 3 + c] * w1;
        }
    } else if (lane == 0) {
        // fallback: row already sorted by k_bcount
        long long prev = -1; int c = 0, mv = -1;
        for (int i = 0; i < n; i++) {
            unsigned long long d = g_bdata[s + i];
            int hv = (int)(d >> 32);
            int slot = (int)(d & 0xffffffffu);
            if (hv != prev) {
                if (occa ^ occ_of(hv)) {
                    int eid = base + c;
                    float t = th[0];
                    float s0 = sdf[lo], s1 = sdf[hv];
                    if (s0 > 0.f && s1 > 0.f) { s0 -= t; s1 -= t; }
                    float inv = 1.f / (s0 - s1);
                    float w0 = -s1 * inv, w1 = s0 * inv;
                    for (int cc = 0; cc < 3; cc++)
                        out[eid * 3 + cc] = pos[lo * 3 + cc] * w0 + pos[hv * 3 + cc] * w1;
                    mv = eid; c++;
                } else mv = -1;
                prev = hv;
            }
            g_idxmap[slot] = mv;
        }
    }
}

__global__ void k_fill_present(int N) {
    int n2 = N + g_meta[4];
    int nw = (n2 + 3) >> 2;
    int i = blockIdx.x * blockDim.x + threadIdx.x;
    if (i < nw) ((int*)g_present)[i] = 0;
}

// fused: faces emission + tetmesh connectivity build + presence marking
__global__ void k_emit(const int4* tet, float* out, int F, int N) {
    int f = blockIdx.x * 256 + threadIdx.x;
    int t = (f < F) ? (int)g_ti[f] : 0;
    int4 cls = cls_block_prefix(t);
    if (f >= F || t == 0) return;
    int4 q = tet[f];
    int qq[4] = {q.x, q.y, q.z, q.w};
    int4* tets4 = (int4*)g_allTets;
    if (t == 15) {
        int NTT3 = g_meta[0] + g_meta[1] - g_meta[2];
        int row = g_meta[2] + 3 * NTT3 + cls.w;
        tets4[row] = q;
#pragma unroll
        for (int j = 0; j < 4; j++) g_present[qq[j]] = 1;
        return;
    }
    int base6 = f * 6;
    int foff = g_meta[6];
    if ((M_NTRI1 >> t) & 1) {
        int row = cls.x;
#pragma unroll
        for (int j = 0; j < 3; j++)
            out[foff + row * 3 + j] = (float)g_idxmap[base6 + c_TRI[t][j]];
    } else {
        int row = g_meta[0] + 2 * cls.y;
#pragma unroll
        for (int j = 0; j < 6; j++)
            out[foff + row * 3 + j] = (float)g_idxmap[base6 + c_TRI[t][j]];
    }
    if ((M_NTET1 >> t) & 1) {
        int row = cls.z;
        int v[4];
#pragma unroll
        for (int j = 0; j < 4; j++) {
            int e = c_TET[t][j];
            v[j] = (e < 4) ? qq[e] : (g_idxmap[base6 + e - 4] + N);
            g_present[v[j]] = 1;
        }
        tets4[row] = make_int4(v[0], v[1], v[2], v[3]);
    } else {
        int row = g_meta[2] + 3 * ((cls.x + cls.y) - cls.z);
#pragma unroll
        for (int rr = 0; rr < 3; rr++) {
            int v[4];
#pragma unroll
            for (int j = 0; j < 4; j++) {
                int e = c_TET[t][rr * 4 + j];
                v[j] = (e < 4) ? qq[e] : (g_idxmap[base6 + e - 4] + N);
                g_present[v[j]] = 1;
            }
            tets4[row + rr] = make_int4(v[0], v[1], v[2], v[3]);
        }
    }
}

__global__ void k_vt(const float* pos, float* out, int N) {
    int n2 = N + g_meta[4];
    int idx = blockIdx.x * blockDim.x + threadIdx.x;
    if (idx >= n2) return;
    if (!g_present[idx]) return;
    int uid = g_presX[idx];
    float x, y, z;
    if (idx < N) {
        x = pos[idx * 3 + 0]; y = pos[idx * 3 + 1]; z = pos[idx * 3 + 2];
    } else {
        int e = idx - N;
        x = out[e * 3 + 0]; y = out[e * 3 + 1]; z = out[e * 3 + 2];
    }
    int o = g_meta[8];
    out[o + uid * 3 + 0] = x;
    out[o + uid * 3 + 1] = y;
    out[o + uid * 3 + 2] = z;
}

__global__ void k_tout(float* out) {
    int row = blockIdx.x * blockDim.x + threadIdx.x;
    if (row >= g_meta[7]) return;
    int4 v = ((const int4*)g_allTets)[row];
    int o = g_meta[9] + row * 4;
    out[o + 0] = (float)g_presX[v.x];
    out[o + 1] = (float)g_presX[v.y];
    out[o + 2] = (float)g_presX[v.z];
    out[o + 3] = (float)g_presX[v.w];
}

// ---------------------------------------------------------------------------
// host launcher
// ---------------------------------------------------------------------------
static inline int gb(long long n) { return (int)((n + 255) / 256); }

extern "C" void kernel_launch(void* const* d_in, const int* in_sizes, int n_in,
                              void* d_out, int out_size) {
    const float* pos = (const float*)d_in[0];
    const float* sdf = (const float*)d_in[1];
    const int4* tet = (const int4*)d_in[2];
    const float* thick = (const float*)d_in[3];
    float* out = (float*)d_out;

    int N = in_sizes[1];
    int F = in_sizes[2] / 4;
    if (N > MAXN) N = MAXN;
    if (F > MAXF) F = MAXF;
    int NW = (N + 31) / 32;
    int PL = N + MAXS;
    int NB = 2 * N;                    // buckets (lo, hi-half)
    int NHALF = N / 2;

    int *p_crossCnt, *p_crossX, *p_bsums;
    cudaGetSymbolAddress((void**)&p_crossCnt, g_crossCnt);
    cudaGetSymbolAddress((void**)&p_crossX, g_crossX);
    cudaGetSymbolAddress((void**)&p_bsums, g_bsums);

    int nbF = (F + 255) / 256;          // tet-domain blocks
    int nbB = (NB + 2047) / 2048;       // bucket-domain scan blocks
    int nbP = (PL + 2047) / 2048;       // presence scan blocks (worst case)

    // 1. occupancy bitmask (+bcnt reset), then fused ti + cls sums + scatter
    k_occbits<<<gb((long long)NW * 32), 256>>>(sdf, thick, N, NW);
    k_ti_scatter<<<nbF, 256>>>(tet, F, NHALF);
    k_scan_singleP<<<1, 1024>>>(nbF);   // -> per-block cls bases + meta[0..3]

    // 2. crossing counts (match_any, no sort) -> prefix -> assignment + verts
    k_bcount<<<gb((long long)NB * 32), 256>>>(NB);
    k_scan_partial_int<<<nbB, 256>>>(p_crossCnt, NB, p_bsums);
    k_scan_single<<<1, 1024>>>(p_bsums, nbB, 1);   // sets E + offsets
    k_scan_final_int<<<nbB, 256>>>(p_crossCnt, NB, p_bsums, p_crossX);
    k_fill_present<<<gb(PL / 4), 256>>>(N);
    k_bemit<<<gb((long long)NB * 32), 256>>>(pos, sdf, thick, out, NB);

    // 3. faces + tets + presence marks (fused)
    k_emit<<<nbF, 256>>>(tet, out, F, N);

    // 4. presence scan over [0, N+E) -> sorted-unique ids (+U, tetsOff)
    k_scan_partial_u8d<<<nbP, 256>>>(N, p_bsums);
    k_scan_single<<<1, 1024>>>(p_bsums, nbP, 2);
    k_scan_final_u8d<<<nbP, 256>>>(N, p_bsums);

    // 5. verts_tetmesh (region 2) + tets_tetmesh (region 3)
    k_vt<<<gb(PL), 256>>>(pos, out, N);
    k_tout<<<gb(MAXTE / 4), 256>>>(out);
}